// round 4
// baseline (speedup 1.0000x reference)
#include <cuda_runtime.h>
#include <cstdint>
#include <cstddef>

#define NBATCH 256
#define NT     2048
#define NFIN   32
#define NHID   64
#define NPOS   (NBATCH * NT)   // 524288

// ---------------- scratch (static device globals: allocation-free) ----------
__device__ float g_env1[(size_t)NBATCH * NT * NHID];   // layer-1 LSTM output
__device__ float g_traj[366 * 8];                      // ODE trajectory

// ---------------- fast activations (fp32, ~1e-6 rel err) -------------------
__device__ __forceinline__ float fsig(float x) {
    return __fdividef(1.0f, 1.0f + __expf(-x));
}
__device__ __forceinline__ float ftanh(float x) {
    float ax = fabsf(x);
    float e  = __expf(-2.0f * ax);
    float r  = __fdividef(1.0f - e, 1.0f + e);
    return copysignf(r, x);
}

// ---------------- ODE body (runs as blockIdx == 0 of the fused kernel) -----
__device__ void ode_body(int tid,
                         const float* __restrict__ h0,
                         const float* __restrict__ W1, const float* __restrict__ b1,
                         const float* __restrict__ W2, const float* __restrict__ b2,
                         const float* __restrict__ W3, const float* __restrict__ b3)
{
    __shared__ float sInp[12];
    __shared__ float sz1[64];
    __shared__ float sz2[64];
    __shared__ float sk[6][8];
    __shared__ float shh[8];
    __shared__ __align__(16) float sW3[8 * 64];
    __shared__ float sb3[8];

    float w1r[9];
    float w2r[64];
    float b1j = 0.f, b2j = 0.f;
    if (tid < 64) {
#pragma unroll
        for (int k = 0; k < 9; ++k) w1r[k] = W1[tid * 9 + k];
#pragma unroll
        for (int k = 0; k < 64; ++k) w2r[k] = W2[tid * 64 + k];
        b1j = b1[tid];
        b2j = b2[tid];
    }
    for (int i = tid; i < 8 * 64; i += 256) sW3[i] = W3[i];
    if (tid < 8) {
        sb3[tid] = b3[tid];
        shh[tid] = h0[tid];
        g_traj[tid] = h0[tid];
    }
    __syncthreads();

    const float dt = 1.0f / 365.0f;

    for (int d = 0; d < 365; ++d) {
        float t0 = (float)d * dt;
#pragma unroll 1
        for (int s = 0; s < 6; ++s) {
            if (tid < 8) {
                float v = shh[tid];
                if (s == 1) v += dt * (0.2f * sk[0][tid]);
                else if (s == 2) v += dt * ((3.f/40.f)*sk[0][tid] + (9.f/40.f)*sk[1][tid]);
                else if (s == 3) v += dt * ((44.f/45.f)*sk[0][tid] - (56.f/15.f)*sk[1][tid] + (32.f/9.f)*sk[2][tid]);
                else if (s == 4) v += dt * ((19372.f/6561.f)*sk[0][tid] - (25360.f/2187.f)*sk[1][tid]
                                          + (64448.f/6561.f)*sk[2][tid] - (212.f/729.f)*sk[3][tid]);
                else if (s == 5) v += dt * ((9017.f/3168.f)*sk[0][tid] - (355.f/33.f)*sk[1][tid]
                                          + (46732.f/5247.f)*sk[2][tid] + (49.f/176.f)*sk[3][tid]
                                          - (5103.f/18656.f)*sk[4][tid]);
                sInp[tid] = v;
            }
            if (tid == 8) {
                float cn;
                if (s == 0) cn = 0.0f;
                else if (s == 1) cn = 0.2f;
                else if (s == 2) cn = 0.3f;
                else if (s == 3) cn = 0.8f;
                else if (s == 4) cn = 8.f/9.f;
                else cn = 1.0f;
                sInp[8] = t0 + cn * dt;
            }
            __syncthreads();
            if (tid < 64) {
                float a = b1j;
#pragma unroll
                for (int k = 0; k < 9; ++k) a = fmaf(w1r[k], sInp[k], a);
                sz1[tid] = ftanh(a);
            }
            __syncthreads();
            if (tid < 64) {
                float a0 = b2j, a1 = 0.f, a2 = 0.f, a3 = 0.f;
#pragma unroll
                for (int k = 0; k < 64; k += 4) {
                    a0 = fmaf(w2r[k+0], sz1[k+0], a0);
                    a1 = fmaf(w2r[k+1], sz1[k+1], a1);
                    a2 = fmaf(w2r[k+2], sz1[k+2], a2);
                    a3 = fmaf(w2r[k+3], sz1[k+3], a3);
                }
                sz2[tid] = ftanh((a0 + a1) + (a2 + a3));
            }
            __syncthreads();
            if (tid < 8) {
                float a0 = sb3[tid], a1 = 0.f, a2 = 0.f, a3 = 0.f;
#pragma unroll
                for (int k = 0; k < 64; k += 4) {
                    a0 = fmaf(sW3[tid*64 + k+0], sz2[k+0], a0);
                    a1 = fmaf(sW3[tid*64 + k+1], sz2[k+1], a1);
                    a2 = fmaf(sW3[tid*64 + k+2], sz2[k+2], a2);
                    a3 = fmaf(sW3[tid*64 + k+3], sz2[k+3], a3);
                }
                sk[s][tid] = (a0 + a1) + (a2 + a3);
            }
            __syncthreads();
        }
        if (tid < 8) {
            float hn = shh[tid] + dt * ((35.f/384.f)   * sk[0][tid]
                                      + (500.f/1113.f) * sk[2][tid]
                                      + (125.f/192.f)  * sk[3][tid]
                                      - (2187.f/6784.f)* sk[4][tid]
                                      + (11.f/84.f)    * sk[5][tid]);
            shh[tid] = hn;
            g_traj[(d + 1) * 8 + tid] = hn;
        }
        __syncthreads();
    }
}

// ---------------- Fused kernel: LSTM L0 + L1 (1-step skew) + hidden ODE -----
// grid = 257 x 256 threads. blockIdx 0: ODE (wave 1). blockIdx 1..256: rows.
// Thread t holds in registers: Wih0 row t (32), Whh0 row t (64),
// Wih1 row t (64), Whh1 row t (64). Per step it computes L0-gate(t) for step s
// and L1-gate(t) for step s-1: two independent dot-product chains.
__global__ __launch_bounds__(256, 1) void k_lstm_fused(
    const float* __restrict__ X,
    const float* __restrict__ Wih0g, const float* __restrict__ Whh0g,
    const float* __restrict__ bih0g, const float* __restrict__ bhh0g,
    const float* __restrict__ Wih1g, const float* __restrict__ Whh1g,
    const float* __restrict__ bih1g, const float* __restrict__ bhh1g,
    const float* __restrict__ h0,
    const float* __restrict__ oW1, const float* __restrict__ ob1,
    const float* __restrict__ oW2, const float* __restrict__ ob2,
    const float* __restrict__ oW3, const float* __restrict__ ob3)
{
    const int t = threadIdx.x;
    if (blockIdx.x == 0) {
        ode_body(t, h0, oW1, ob1, oW2, ob2, oW3, ob3);
        return;
    }
    const int b = blockIdx.x - 1;

    float wih0[NFIN];
#pragma unroll
    for (int k = 0; k < NFIN; ++k) wih0[k] = Wih0g[t * NFIN + k];
    float whh0[NHID];
#pragma unroll
    for (int k = 0; k < NHID; ++k) whh0[k] = Whh0g[t * NHID + k];
    float wih1[NHID];
#pragma unroll
    for (int k = 0; k < NHID; ++k) wih1[k] = Wih1g[t * NHID + k];
    float whh1[NHID];
#pragma unroll
    for (int k = 0; k < NHID; ++k) whh1[k] = Whh1g[t * NHID + k];
    const float bias0 = bih0g[t] + bhh0g[t];
    const float bias1 = bih1g[t] + bhh1g[t];

    __shared__ __align__(16) float xs[2][NFIN];
    __shared__ float act0[256];
    __shared__ float act1[256];
    __shared__ __align__(16) float hs0[NHID];
    __shared__ __align__(16) float hs1[NHID];
    if (t < NHID) { hs0[t] = 0.0f; hs1[t] = 0.0f; }

    const float* xrow = X + (size_t)b * NT * NFIN;
    if (t < 8) ((float4*)xs[0])[t] = ((const float4*)xrow)[t];
    __syncthreads();

    float c = 0.0f;                       // c0 for t<64, c1 for 64<=t<128
    float* eout = g_env1 + (size_t)b * NT * NHID;
    const bool is_tanh_gate = (t >= 128 && t < 192);

    for (int s = 0; s <= NT; ++s) {
        const int cur = s & 1;
        if (s < NT) {
            // prefetch next x
            if (t < 8) {
                int nxt = (s + 1 < NT) ? (s + 1) : s;
                ((float4*)xs[cur ^ 1])[t] = ((const float4*)(xrow + (size_t)nxt * NFIN))[t];
            }
            // L0 gate t for step s: Wih0 . x[s] + Whh0 . h0(s-1)
            float a0 = bias0, a1 = 0.f, a2 = 0.f, a3 = 0.f;
#pragma unroll
            for (int k = 0; k < NFIN; k += 4) {
                float4 v = *(const float4*)(xs[cur] + k);
                a0 = fmaf(wih0[k+0], v.x, a0);
                a1 = fmaf(wih0[k+1], v.y, a1);
                a2 = fmaf(wih0[k+2], v.z, a2);
                a3 = fmaf(wih0[k+3], v.w, a3);
            }
#pragma unroll
            for (int k = 0; k < NHID; k += 4) {
                float4 v = *(const float4*)(hs0 + k);
                a0 = fmaf(whh0[k+0], v.x, a0);
                a1 = fmaf(whh0[k+1], v.y, a1);
                a2 = fmaf(whh0[k+2], v.z, a2);
                a3 = fmaf(whh0[k+3], v.w, a3);
            }
            float g = (a0 + a1) + (a2 + a3);
            act0[t] = is_tanh_gate ? ftanh(g) : fsig(g);
        }
        if (s >= 1) {
            // L1 gate t for step s-1: Wih1 . h0(s-1) + Whh1 . h1(s-2)
            float a0 = bias1, a1 = 0.f, a2 = 0.f, a3 = 0.f;
#pragma unroll
            for (int k = 0; k < NHID; k += 4) {
                float4 v = *(const float4*)(hs0 + k);
                a0 = fmaf(wih1[k+0], v.x, a0);
                a1 = fmaf(wih1[k+1], v.y, a1);
                a2 = fmaf(wih1[k+2], v.z, a2);
                a3 = fmaf(wih1[k+3], v.w, a3);
            }
#pragma unroll
            for (int k = 0; k < NHID; k += 4) {
                float4 v = *(const float4*)(hs1 + k);
                a0 = fmaf(whh1[k+0], v.x, a0);
                a1 = fmaf(whh1[k+1], v.y, a1);
                a2 = fmaf(whh1[k+2], v.z, a2);
                a3 = fmaf(whh1[k+3], v.w, a3);
            }
            float g = (a0 + a1) + (a2 + a3);
            act1[t] = is_tanh_gate ? ftanh(g) : fsig(g);
        }
        __syncthreads();
        if (t < NHID) {
            if (s < NT) {
                c = act0[64 + t] * c + act0[t] * act0[128 + t];
                hs0[t] = act0[192 + t] * ftanh(c);
            }
        } else if (t < 2 * NHID) {
            if (s >= 1) {
                const int j = t - NHID;
                c = act1[64 + j] * c + act1[j] * act1[128 + j];
                float h = act1[192 + j] * ftanh(c);
                hs1[j] = h;
                eout[(size_t)(s - 1) * NHID + j] = h;
            }
        }
        __syncthreads();
    }
}

// ---------------- Kernel C: physics + fusion MLP + outputs ------------------
__global__ __launch_bounds__(256) void k_fusion(
    const int*   __restrict__ day_ids,
    const float* __restrict__ raw,
    const float* __restrict__ hdw, const float* __restrict__ hdb,
    const float* __restrict__ fW1, const float* __restrict__ fb1,
    const float* __restrict__ fW2, const float* __restrict__ fb2,
    const float* __restrict__ rW1, const float* __restrict__ rb1,
    const float* __restrict__ rW2, const float* __restrict__ rb2,
    float* __restrict__ out)
{
    const int tid = threadIdx.x;

    __shared__ __align__(16) float sW1[64 * 76];   // fus_W1 padded 73 -> 76
    __shared__ __align__(16) float sW2[64 * 64];
    __shared__ __align__(16) float sR1[32 * 64];
    __shared__ float sR2[32];
    __shared__ float sb1[64], sb2[64], srb1[32];
    __shared__ float shdw[8];
    __shared__ float sscal[2];

    for (int i = tid; i < 64 * 76; i += 256) {
        int j = i / 76, k = i - j * 76;
        sW1[i] = (k < 73) ? fW1[j * 73 + k] : 0.0f;
    }
    for (int i = tid; i < 64 * 64; i += 256) sW2[i] = fW2[i];
    for (int i = tid; i < 32 * 64; i += 256) sR1[i] = rW1[i];
    if (tid < 64) { sb1[tid] = fb1[tid]; sb2[tid] = fb2[tid]; }
    if (tid < 32) { sR2[tid] = rW2[tid]; srb1[tid] = rb1[tid]; }
    if (tid < 8)  shdw[tid] = hdw[tid];
    if (tid == 0) { sscal[0] = hdb[0]; sscal[1] = rb2[0]; }
    __syncthreads();

    const int idx = blockIdx.x * 256 + tid;       // grid = 2048 -> idx < NPOS
    const int b = idx >> 11;

    float z[76];
    const float4* ep = (const float4*)(g_env1 + (size_t)idx * NHID);
#pragma unroll
    for (int i = 0; i < 16; ++i) {
        float4 v = ep[i];
        z[4*i+0] = v.x; z[4*i+1] = v.y; z[4*i+2] = v.z; z[4*i+3] = v.w;
    }
    const int day = day_ids[b];
    float health[8];
#pragma unroll
    for (int i = 0; i < 8; ++i) { health[i] = g_traj[day * 8 + i]; z[64 + i] = health[i]; }

    float4 rv = ((const float4*)raw)[idx];
    float iphys = rv.x * 9.0f * (1.0f + 0.0005f * (rv.y - 0.5f));
    z[72] = iphys; z[73] = 0.f; z[74] = 0.f; z[75] = 0.f;

    float rawD = sscal[0];
#pragma unroll
    for (int i = 0; i < 8; ++i) rawD = fmaf(health[i], shdw[i], rawD);
    float D = fsig(rawD);

    // feat1 = relu(fus_W1 @ z + fb1)
    float f1[64];
#pragma unroll
    for (int j = 0; j < 64; j += 4) {
        float a0 = sb1[j], a1 = sb1[j+1], a2 = sb1[j+2], a3 = sb1[j+3];
#pragma unroll
        for (int k = 0; k < 76; k += 4) {
            float4 w0 = *(const float4*)(sW1 + (j+0) * 76 + k);
            float4 w1 = *(const float4*)(sW1 + (j+1) * 76 + k);
            float4 w2 = *(const float4*)(sW1 + (j+2) * 76 + k);
            float4 w3 = *(const float4*)(sW1 + (j+3) * 76 + k);
            a0 = fmaf(z[k], w0.x, a0); a0 = fmaf(z[k+1], w0.y, a0); a0 = fmaf(z[k+2], w0.z, a0); a0 = fmaf(z[k+3], w0.w, a0);
            a1 = fmaf(z[k], w1.x, a1); a1 = fmaf(z[k+1], w1.y, a1); a1 = fmaf(z[k+2], w1.z, a1); a1 = fmaf(z[k+3], w1.w, a1);
            a2 = fmaf(z[k], w2.x, a2); a2 = fmaf(z[k+1], w2.y, a2); a2 = fmaf(z[k+2], w2.z, a2); a2 = fmaf(z[k+3], w2.w, a2);
            a3 = fmaf(z[k], w3.x, a3); a3 = fmaf(z[k+1], w3.y, a3); a3 = fmaf(z[k+2], w3.z, a3); a3 = fmaf(z[k+3], w3.w, a3);
        }
        f1[j+0] = fmaxf(a0, 0.f); f1[j+1] = fmaxf(a1, 0.f);
        f1[j+2] = fmaxf(a2, 0.f); f1[j+3] = fmaxf(a3, 0.f);
    }

    // feat2 = relu(fus_W2 @ feat1 + fb2)
    float f2[64];
#pragma unroll
    for (int j = 0; j < 64; j += 4) {
        float a0 = sb2[j], a1 = sb2[j+1], a2 = sb2[j+2], a3 = sb2[j+3];
#pragma unroll
        for (int k = 0; k < 64; k += 4) {
            float4 w0 = *(const float4*)(sW2 + (j+0) * 64 + k);
            float4 w1 = *(const float4*)(sW2 + (j+1) * 64 + k);
            float4 w2 = *(const float4*)(sW2 + (j+2) * 64 + k);
            float4 w3 = *(const float4*)(sW2 + (j+3) * 64 + k);
            a0 = fmaf(f1[k], w0.x, a0); a0 = fmaf(f1[k+1], w0.y, a0); a0 = fmaf(f1[k+2], w0.z, a0); a0 = fmaf(f1[k+3], w0.w, a0);
            a1 = fmaf(f1[k], w1.x, a1); a1 = fmaf(f1[k+1], w1.y, a1); a1 = fmaf(f1[k+2], w1.z, a1); a1 = fmaf(f1[k+3], w1.w, a1);
            a2 = fmaf(f1[k], w2.x, a2); a2 = fmaf(f1[k+1], w2.y, a2); a2 = fmaf(f1[k+2], w2.z, a2); a2 = fmaf(f1[k+3], w2.w, a2);
            a3 = fmaf(f1[k], w3.x, a3); a3 = fmaf(f1[k+1], w3.y, a3); a3 = fmaf(f1[k+2], w3.z, a3); a3 = fmaf(f1[k+3], w3.w, a3);
        }
        f2[j+0] = fmaxf(a0, 0.f); f2[j+1] = fmaxf(a1, 0.f);
        f2[j+2] = fmaxf(a2, 0.f); f2[j+3] = fmaxf(a3, 0.f);
    }

    // r1 = relu(res_W1 @ feat2 + rb1)
    float r1[32];
#pragma unroll
    for (int j = 0; j < 32; j += 4) {
        float a0 = srb1[j], a1 = srb1[j+1], a2 = srb1[j+2], a3 = srb1[j+3];
#pragma unroll
        for (int k = 0; k < 64; k += 4) {
            float4 w0 = *(const float4*)(sR1 + (j+0) * 64 + k);
            float4 w1 = *(const float4*)(sR1 + (j+1) * 64 + k);
            float4 w2 = *(const float4*)(sR1 + (j+2) * 64 + k);
            float4 w3 = *(const float4*)(sR1 + (j+3) * 64 + k);
            a0 = fmaf(f2[k], w0.x, a0); a0 = fmaf(f2[k+1], w0.y, a0); a0 = fmaf(f2[k+2], w0.z, a0); a0 = fmaf(f2[k+3], w0.w, a0);
            a1 = fmaf(f2[k], w1.x, a1); a1 = fmaf(f2[k+1], w1.y, a1); a1 = fmaf(f2[k+2], w1.z, a1); a1 = fmaf(f2[k+3], w1.w, a1);
            a2 = fmaf(f2[k], w2.x, a2); a2 = fmaf(f2[k+1], w2.y, a2); a2 = fmaf(f2[k+2], w2.z, a2); a2 = fmaf(f2[k+3], w2.w, a2);
            a3 = fmaf(f2[k], w3.x, a3); a3 = fmaf(f2[k+1], w3.y, a3); a3 = fmaf(f2[k+2], w3.z, a3); a3 = fmaf(f2[k+3], w3.w, a3);
        }
        r1[j+0] = fmaxf(a0, 0.f); r1[j+1] = fmaxf(a1, 0.f);
        r1[j+2] = fmaxf(a2, 0.f); r1[j+3] = fmaxf(a3, 0.f);
    }

    // r = res_W2 @ r1 + rb2
    float a0 = sscal[1], a1 = 0.f, a2 = 0.f, a3 = 0.f;
#pragma unroll
    for (int k = 0; k < 32; k += 4) {
        a0 = fmaf(r1[k+0], sR2[k+0], a0);
        a1 = fmaf(r1[k+1], sR2[k+1], a1);
        a2 = fmaf(r1[k+2], sR2[k+2], a2);
        a3 = fmaf(r1[k+3], sR2[k+3], a3);
    }
    float r = (a0 + a1) + (a2 + a3);

    float ibase = D * iphys;
    out[(size_t)0 * NPOS + idx] = ibase + r;   // I_pred
    out[(size_t)1 * NPOS + idx] = iphys;       // I_phys
    out[(size_t)2 * NPOS + idx] = ibase;       // I_base
    out[(size_t)3 * NPOS + idx] = D;           // D
    out[(size_t)4 * NPOS + idx] = r;           // r
    float* ho = out + (size_t)5 * NPOS + (size_t)idx * 8;
#pragma unroll
    for (int i = 0; i < 8; ++i) ho[i] = health[i];  // health_seq
}

// ---------------- launch ----------------------------------------------------
extern "C" void kernel_launch(void* const* d_in, const int* in_sizes, int n_in,
                              void* d_out, int out_size)
{
    const float* X        = (const float*)d_in[0];
    const int*   day_ids  = (const int*)  d_in[1];
    const float* raw      = (const float*)d_in[2];
    const float* ih0      = (const float*)d_in[3];
    const float* oW1      = (const float*)d_in[4];
    const float* ob1      = (const float*)d_in[5];
    const float* oW2      = (const float*)d_in[6];
    const float* ob2      = (const float*)d_in[7];
    const float* oW3      = (const float*)d_in[8];
    const float* ob3      = (const float*)d_in[9];
    const float* Wih0     = (const float*)d_in[10];
    const float* Whh0     = (const float*)d_in[11];
    const float* bih0     = (const float*)d_in[12];
    const float* bhh0     = (const float*)d_in[13];
    const float* Wih1     = (const float*)d_in[14];
    const float* Whh1     = (const float*)d_in[15];
    const float* bih1     = (const float*)d_in[16];
    const float* bhh1     = (const float*)d_in[17];
    const float* hdw      = (const float*)d_in[18];
    const float* hdb      = (const float*)d_in[19];
    const float* fW1      = (const float*)d_in[20];
    const float* fb1      = (const float*)d_in[21];
    const float* fW2      = (const float*)d_in[22];
    const float* fb2      = (const float*)d_in[23];
    const float* rW1      = (const float*)d_in[24];
    const float* rb1      = (const float*)d_in[25];
    const float* rW2      = (const float*)d_in[26];
    const float* rb2      = (const float*)d_in[27];

    // Fused 2-layer LSTM (1-step pipeline skew) + ODE as CTA 0.
    k_lstm_fused<<<NBATCH + 1, 256>>>(X,
                                      Wih0, Whh0, bih0, bhh0,
                                      Wih1, Whh1, bih1, bhh1,
                                      ih0, oW1, ob1, oW2, ob2, oW3, ob3);
    // Physics + fusion MLP + all outputs.
    k_fusion<<<NPOS / 256, 256>>>(day_ids, raw, hdw, hdb,
                                  fW1, fb1, fW2, fb2,
                                  rW1, rb1, rW2, rb2,
                                  (float*)d_out);
}

// round 5
// speedup vs baseline: 1.3065x; 1.3065x over previous
#include <cuda_runtime.h>
#include <cstdint>
#include <cstddef>

#define NBATCH 256
#define NT     2048
#define NFIN   32
#define NHID   64
#define NPOS   (NBATCH * NT)   // 524288

// ---------------- scratch (static device globals: allocation-free) ----------
__device__ float g_env0[(size_t)NBATCH * NT * NHID];   // layer-0 LSTM output
__device__ float g_env1[(size_t)NBATCH * NT * NHID];   // layer-1 LSTM output
__device__ float g_traj[366 * 8];                      // ODE trajectory

// ---------------- fast activations (fp32, ~1e-6 rel err) -------------------
__device__ __forceinline__ float fsig(float x) {
    return __fdividef(1.0f, 1.0f + __expf(-x));
}
__device__ __forceinline__ float ftanh(float x) {
    float ax = fabsf(x);
    float e  = __expf(-2.0f * ax);
    float r  = __fdividef(1.0f - e, 1.0f + e);
    return copysignf(r, x);
}

// ---------------- ODE body (runs as blockIdx == 128 of kernel L0) ----------
__device__ void ode_body(int tid,
                         const float* __restrict__ h0,
                         const float* __restrict__ W1, const float* __restrict__ b1,
                         const float* __restrict__ W2, const float* __restrict__ b2,
                         const float* __restrict__ W3, const float* __restrict__ b3)
{
    __shared__ float sInp[12];
    __shared__ float sz1[64];
    __shared__ float sz2[64];
    __shared__ float sk[6][8];
    __shared__ float shh[8];
    __shared__ __align__(16) float sW3[8 * 64];
    __shared__ float sb3[8];

    float w1r[9];
    float w2r[64];
    float b1j = 0.f, b2j = 0.f;
    if (tid < 64) {
#pragma unroll
        for (int k = 0; k < 9; ++k) w1r[k] = W1[tid * 9 + k];
#pragma unroll
        for (int k = 0; k < 64; ++k) w2r[k] = W2[tid * 64 + k];
        b1j = b1[tid];
        b2j = b2[tid];
    }
    for (int i = tid; i < 8 * 64; i += 256) sW3[i] = W3[i];
    if (tid < 8) {
        sb3[tid] = b3[tid];
        shh[tid] = h0[tid];
        g_traj[tid] = h0[tid];
    }
    __syncthreads();

    const float dt = 1.0f / 365.0f;

    for (int d = 0; d < 365; ++d) {
        float t0 = (float)d * dt;
#pragma unroll 1
        for (int s = 0; s < 6; ++s) {
            if (tid < 8) {
                float v = shh[tid];
                if (s == 1) v += dt * (0.2f * sk[0][tid]);
                else if (s == 2) v += dt * ((3.f/40.f)*sk[0][tid] + (9.f/40.f)*sk[1][tid]);
                else if (s == 3) v += dt * ((44.f/45.f)*sk[0][tid] - (56.f/15.f)*sk[1][tid] + (32.f/9.f)*sk[2][tid]);
                else if (s == 4) v += dt * ((19372.f/6561.f)*sk[0][tid] - (25360.f/2187.f)*sk[1][tid]
                                          + (64448.f/6561.f)*sk[2][tid] - (212.f/729.f)*sk[3][tid]);
                else if (s == 5) v += dt * ((9017.f/3168.f)*sk[0][tid] - (355.f/33.f)*sk[1][tid]
                                          + (46732.f/5247.f)*sk[2][tid] + (49.f/176.f)*sk[3][tid]
                                          - (5103.f/18656.f)*sk[4][tid]);
                sInp[tid] = v;
            }
            if (tid == 8) {
                float cn;
                if (s == 0) cn = 0.0f;
                else if (s == 1) cn = 0.2f;
                else if (s == 2) cn = 0.3f;
                else if (s == 3) cn = 0.8f;
                else if (s == 4) cn = 8.f/9.f;
                else cn = 1.0f;
                sInp[8] = t0 + cn * dt;
            }
            __syncthreads();
            if (tid < 64) {
                float a = b1j;
#pragma unroll
                for (int k = 0; k < 9; ++k) a = fmaf(w1r[k], sInp[k], a);
                sz1[tid] = ftanh(a);
            }
            __syncthreads();
            if (tid < 64) {
                float a0 = b2j, a1 = 0.f, a2 = 0.f, a3 = 0.f;
#pragma unroll
                for (int k = 0; k < 64; k += 4) {
                    a0 = fmaf(w2r[k+0], sz1[k+0], a0);
                    a1 = fmaf(w2r[k+1], sz1[k+1], a1);
                    a2 = fmaf(w2r[k+2], sz1[k+2], a2);
                    a3 = fmaf(w2r[k+3], sz1[k+3], a3);
                }
                sz2[tid] = ftanh((a0 + a1) + (a2 + a3));
            }
            __syncthreads();
            if (tid < 8) {
                float a0 = sb3[tid], a1 = 0.f, a2 = 0.f, a3 = 0.f;
#pragma unroll
                for (int k = 0; k < 64; k += 4) {
                    a0 = fmaf(sW3[tid*64 + k+0], sz2[k+0], a0);
                    a1 = fmaf(sW3[tid*64 + k+1], sz2[k+1], a1);
                    a2 = fmaf(sW3[tid*64 + k+2], sz2[k+2], a2);
                    a3 = fmaf(sW3[tid*64 + k+3], sz2[k+3], a3);
                }
                sk[s][tid] = (a0 + a1) + (a2 + a3);
            }
            __syncthreads();
        }
        if (tid < 8) {
            float hn = shh[tid] + dt * ((35.f/384.f)   * sk[0][tid]
                                      + (500.f/1113.f) * sk[2][tid]
                                      + (125.f/192.f)  * sk[3][tid]
                                      - (2187.f/6784.f)* sk[4][tid]
                                      + (11.f/84.f)    * sk[5][tid]);
            shh[tid] = hn;
            g_traj[(d + 1) * 8 + tid] = hn;
        }
        __syncthreads();
    }
}

// ============================================================================
// LSTM layer 0: 128 CTAs x 256 thr, 2 batch rows per CTA, + ODE as CTA 128.
// Thread -> (gate gt, unit u): warp w holds units w*8..w*8+7, lane l:
// gt = l>>3, u = (w<<3)|(l&7). Weight row r = gt*64+u in registers.
// Cell update done in-warp via shfl (c replicated across the 4 gate lanes).
// hs ping-pong => single __syncthreads per step.
// ============================================================================
__global__ __launch_bounds__(256, 1) void k_lstm0(
    const float* __restrict__ X,
    const float* __restrict__ Wih, const float* __restrict__ Whh,
    const float* __restrict__ bih, const float* __restrict__ bhh,
    const float* __restrict__ h0,
    const float* __restrict__ oW1, const float* __restrict__ ob1,
    const float* __restrict__ oW2, const float* __restrict__ ob2,
    const float* __restrict__ oW3, const float* __restrict__ ob3)
{
    const int t = threadIdx.x;
    if (blockIdx.x == 128) {
        ode_body(t, h0, oW1, ob1, oW2, ob2, oW3, ob3);
        return;
    }
    const int w  = t >> 5, l = t & 31;
    const int gt = l >> 3;
    const int u  = (w << 3) | (l & 7);
    const int r  = gt * 64 + u;
    const int lb = l & 7;

    float wih[NFIN];
#pragma unroll
    for (int k = 0; k < NFIN; ++k) wih[k] = Wih[r * NFIN + k];
    float whh[NHID];
#pragma unroll
    for (int k = 0; k < NHID; ++k) whh[k] = Whh[r * NHID + k];
    const float bias = bih[r] + bhh[r];

    __shared__ __align__(16) float xs[2][2][NFIN];   // [buf][row][k]
    __shared__ __align__(16) float hs[2][2][NHID];   // [buf][row][u]
    if (t < 128) hs[0][t >> 6][t & 63] = 0.0f;

    const int b0 = blockIdx.x * 2;
    const float* x0 = X + (size_t)b0 * NT * NFIN;
    const float* x1 = x0 + (size_t)NT * NFIN;
    if (t < 16) {
        const float* xr = (t < 8) ? x0 : x1;
        ((float4*)xs[0][t >> 3])[t & 7] = ((const float4*)xr)[t & 7];
    }
    __syncthreads();

    float cA = 0.0f, cB = 0.0f;
    float* e0 = g_env0 + (size_t)b0 * NT * NHID;
    float* e1 = e0 + (size_t)NT * NHID;
    const bool isg = (gt == 2);

    for (int s = 0; s < NT; ++s) {
        const int cur = s & 1;
        if (t < 16) {
            int nxt = (s + 1 < NT) ? (s + 1) : s;
            const float* xr = (t < 8) ? x0 : x1;
            ((float4*)xs[cur ^ 1][t >> 3])[t & 7] =
                ((const float4*)(xr + (size_t)nxt * NFIN))[t & 7];
        }
        float aA0 = bias, aA1 = 0.f, aA2 = 0.f, aA3 = 0.f;
        float aB0 = bias, aB1 = 0.f, aB2 = 0.f, aB3 = 0.f;
#pragma unroll
        for (int k = 0; k < NFIN; k += 4) {
            float4 vA = *(const float4*)(xs[cur][0] + k);
            float4 vB = *(const float4*)(xs[cur][1] + k);
            aA0 = fmaf(wih[k+0], vA.x, aA0);  aB0 = fmaf(wih[k+0], vB.x, aB0);
            aA1 = fmaf(wih[k+1], vA.y, aA1);  aB1 = fmaf(wih[k+1], vB.y, aB1);
            aA2 = fmaf(wih[k+2], vA.z, aA2);  aB2 = fmaf(wih[k+2], vB.z, aB2);
            aA3 = fmaf(wih[k+3], vA.w, aA3);  aB3 = fmaf(wih[k+3], vB.w, aB3);
        }
#pragma unroll
        for (int k = 0; k < NHID; k += 4) {
            float4 vA = *(const float4*)(hs[cur][0] + k);
            float4 vB = *(const float4*)(hs[cur][1] + k);
            aA0 = fmaf(whh[k+0], vA.x, aA0);  aB0 = fmaf(whh[k+0], vB.x, aB0);
            aA1 = fmaf(whh[k+1], vA.y, aA1);  aB1 = fmaf(whh[k+1], vB.y, aB1);
            aA2 = fmaf(whh[k+2], vA.z, aA2);  aB2 = fmaf(whh[k+2], vB.z, aB2);
            aA3 = fmaf(whh[k+3], vA.w, aA3);  aB3 = fmaf(whh[k+3], vB.w, aB3);
        }
        float pA = (aA0 + aA1) + (aA2 + aA3);
        float pB = (aB0 + aB1) + (aB2 + aB3);
        float actA = isg ? ftanh(pA) : fsig(pA);
        float actB = isg ? ftanh(pB) : fsig(pB);

        float iA = __shfl_sync(0xffffffffu, actA, lb);
        float fA = __shfl_sync(0xffffffffu, actA, lb + 8);
        float gA = __shfl_sync(0xffffffffu, actA, lb + 16);
        float oA = __shfl_sync(0xffffffffu, actA, lb + 24);
        float iB = __shfl_sync(0xffffffffu, actB, lb);
        float fB = __shfl_sync(0xffffffffu, actB, lb + 8);
        float gB = __shfl_sync(0xffffffffu, actB, lb + 16);
        float oB = __shfl_sync(0xffffffffu, actB, lb + 24);

        cA = fA * cA + iA * gA;
        cB = fB * cB + iB * gB;
        float hA = oA * ftanh(cA);
        float hB = oB * ftanh(cB);

        if (gt == 0) {
            hs[cur ^ 1][0][u] = hA;
            hs[cur ^ 1][1][u] = hB;
            e0[(size_t)s * NHID + u] = hA;
            e1[(size_t)s * NHID + u] = hB;
        }
        __syncthreads();
    }
}

// ============================================================================
// LSTM layer 1: 128 CTAs x 256 thr, 2 rows per CTA. Same structure; input
// is the 64-wide g_env0 stream, output g_env1.
// ============================================================================
__global__ __launch_bounds__(256, 1) void k_lstm1(
    const float* __restrict__ Wih, const float* __restrict__ Whh,
    const float* __restrict__ bih, const float* __restrict__ bhh)
{
    const int t = threadIdx.x;
    const int w  = t >> 5, l = t & 31;
    const int gt = l >> 3;
    const int u  = (w << 3) | (l & 7);
    const int r  = gt * 64 + u;
    const int lb = l & 7;

    float wih[NHID];
#pragma unroll
    for (int k = 0; k < NHID; ++k) wih[k] = Wih[r * NHID + k];
    float whh[NHID];
#pragma unroll
    for (int k = 0; k < NHID; ++k) whh[k] = Whh[r * NHID + k];
    const float bias = bih[r] + bhh[r];

    __shared__ __align__(16) float xs[2][2][NHID];   // [buf][row][k]
    __shared__ __align__(16) float hs[2][2][NHID];
    if (t < 128) hs[0][t >> 6][t & 63] = 0.0f;

    const int b0 = blockIdx.x * 2;
    const float* x0 = g_env0 + (size_t)b0 * NT * NHID;
    const float* x1 = x0 + (size_t)NT * NHID;
    if (t < 32) {
        const float* xr = (t < 16) ? x0 : x1;
        ((float4*)xs[0][t >> 4])[t & 15] = ((const float4*)xr)[t & 15];
    }
    __syncthreads();

    float cA = 0.0f, cB = 0.0f;
    float* e0 = g_env1 + (size_t)b0 * NT * NHID;
    float* e1 = e0 + (size_t)NT * NHID;
    const bool isg = (gt == 2);

    for (int s = 0; s < NT; ++s) {
        const int cur = s & 1;
        if (t < 32) {
            int nxt = (s + 1 < NT) ? (s + 1) : s;
            const float* xr = (t < 16) ? x0 : x1;
            ((float4*)xs[cur ^ 1][t >> 4])[t & 15] =
                ((const float4*)(xr + (size_t)nxt * NHID))[t & 15];
        }
        float aA0 = bias, aA1 = 0.f, aA2 = 0.f, aA3 = 0.f;
        float aB0 = bias, aB1 = 0.f, aB2 = 0.f, aB3 = 0.f;
#pragma unroll
        for (int k = 0; k < NHID; k += 4) {
            float4 vA = *(const float4*)(xs[cur][0] + k);
            float4 vB = *(const float4*)(xs[cur][1] + k);
            aA0 = fmaf(wih[k+0], vA.x, aA0);  aB0 = fmaf(wih[k+0], vB.x, aB0);
            aA1 = fmaf(wih[k+1], vA.y, aA1);  aB1 = fmaf(wih[k+1], vB.y, aB1);
            aA2 = fmaf(wih[k+2], vA.z, aA2);  aB2 = fmaf(wih[k+2], vB.z, aB2);
            aA3 = fmaf(wih[k+3], vA.w, aA3);  aB3 = fmaf(wih[k+3], vB.w, aB3);
        }
#pragma unroll
        for (int k = 0; k < NHID; k += 4) {
            float4 vA = *(const float4*)(hs[cur][0] + k);
            float4 vB = *(const float4*)(hs[cur][1] + k);
            aA0 = fmaf(whh[k+0], vA.x, aA0);  aB0 = fmaf(whh[k+0], vB.x, aB0);
            aA1 = fmaf(whh[k+1], vA.y, aA1);  aB1 = fmaf(whh[k+1], vB.y, aB1);
            aA2 = fmaf(whh[k+2], vA.z, aA2);  aB2 = fmaf(whh[k+2], vB.z, aB2);
            aA3 = fmaf(whh[k+3], vA.w, aA3);  aB3 = fmaf(whh[k+3], vB.w, aB3);
        }
        float pA = (aA0 + aA1) + (aA2 + aA3);
        float pB = (aB0 + aB1) + (aB2 + aB3);
        float actA = isg ? ftanh(pA) : fsig(pA);
        float actB = isg ? ftanh(pB) : fsig(pB);

        float iA = __shfl_sync(0xffffffffu, actA, lb);
        float fA = __shfl_sync(0xffffffffu, actA, lb + 8);
        float gA = __shfl_sync(0xffffffffu, actA, lb + 16);
        float oA = __shfl_sync(0xffffffffu, actA, lb + 24);
        float iB = __shfl_sync(0xffffffffu, actB, lb);
        float fB = __shfl_sync(0xffffffffu, actB, lb + 8);
        float gB = __shfl_sync(0xffffffffu, actB, lb + 16);
        float oB = __shfl_sync(0xffffffffu, actB, lb + 24);

        cA = fA * cA + iA * gA;
        cB = fB * cB + iB * gB;
        float hA = oA * ftanh(cA);
        float hB = oB * ftanh(cB);

        if (gt == 0) {
            hs[cur ^ 1][0][u] = hA;
            hs[cur ^ 1][1][u] = hB;
            e0[(size_t)s * NHID + u] = hA;
            e1[(size_t)s * NHID + u] = hB;
        }
        __syncthreads();
    }
}

// ---------------- Kernel C: physics + fusion MLP + outputs ------------------
__global__ __launch_bounds__(256) void k_fusion(
    const int*   __restrict__ day_ids,
    const float* __restrict__ raw,
    const float* __restrict__ hdw, const float* __restrict__ hdb,
    const float* __restrict__ fW1, const float* __restrict__ fb1,
    const float* __restrict__ fW2, const float* __restrict__ fb2,
    const float* __restrict__ rW1, const float* __restrict__ rb1,
    const float* __restrict__ rW2, const float* __restrict__ rb2,
    float* __restrict__ out)
{
    const int tid = threadIdx.x;

    __shared__ __align__(16) float sW1[64 * 76];   // fus_W1 padded 73 -> 76
    __shared__ __align__(16) float sW2[64 * 64];
    __shared__ __align__(16) float sR1[32 * 64];
    __shared__ float sR2[32];
    __shared__ float sb1[64], sb2[64], srb1[32];
    __shared__ float shdw[8];
    __shared__ float sscal[2];

    for (int i = tid; i < 64 * 76; i += 256) {
        int j = i / 76, k = i - j * 76;
        sW1[i] = (k < 73) ? fW1[j * 73 + k] : 0.0f;
    }
    for (int i = tid; i < 64 * 64; i += 256) sW2[i] = fW2[i];
    for (int i = tid; i < 32 * 64; i += 256) sR1[i] = rW1[i];
    if (tid < 64) { sb1[tid] = fb1[tid]; sb2[tid] = fb2[tid]; }
    if (tid < 32) { sR2[tid] = rW2[tid]; srb1[tid] = rb1[tid]; }
    if (tid < 8)  shdw[tid] = hdw[tid];
    if (tid == 0) { sscal[0] = hdb[0]; sscal[1] = rb2[0]; }
    __syncthreads();

    const int idx = blockIdx.x * 256 + tid;       // grid = 2048 -> idx < NPOS
    const int b = idx >> 11;

    float z[76];
    const float4* ep = (const float4*)(g_env1 + (size_t)idx * NHID);
#pragma unroll
    for (int i = 0; i < 16; ++i) {
        float4 v = ep[i];
        z[4*i+0] = v.x; z[4*i+1] = v.y; z[4*i+2] = v.z; z[4*i+3] = v.w;
    }
    const int day = day_ids[b];
    float health[8];
#pragma unroll
    for (int i = 0; i < 8; ++i) { health[i] = g_traj[day * 8 + i]; z[64 + i] = health[i]; }

    float4 rv = ((const float4*)raw)[idx];
    float iphys = rv.x * 9.0f * (1.0f + 0.0005f * (rv.y - 0.5f));
    z[72] = iphys; z[73] = 0.f; z[74] = 0.f; z[75] = 0.f;

    float rawD = sscal[0];
#pragma unroll
    for (int i = 0; i < 8; ++i) rawD = fmaf(health[i], shdw[i], rawD);
    float D = fsig(rawD);

    // feat1 = relu(fus_W1 @ z + fb1)
    float f1[64];
#pragma unroll
    for (int j = 0; j < 64; j += 4) {
        float a0 = sb1[j], a1 = sb1[j+1], a2 = sb1[j+2], a3 = sb1[j+3];
#pragma unroll
        for (int k = 0; k < 76; k += 4) {
            float4 w0 = *(const float4*)(sW1 + (j+0) * 76 + k);
            float4 w1 = *(const float4*)(sW1 + (j+1) * 76 + k);
            float4 w2 = *(const float4*)(sW1 + (j+2) * 76 + k);
            float4 w3 = *(const float4*)(sW1 + (j+3) * 76 + k);
            a0 = fmaf(z[k], w0.x, a0); a0 = fmaf(z[k+1], w0.y, a0); a0 = fmaf(z[k+2], w0.z, a0); a0 = fmaf(z[k+3], w0.w, a0);
            a1 = fmaf(z[k], w1.x, a1); a1 = fmaf(z[k+1], w1.y, a1); a1 = fmaf(z[k+2], w1.z, a1); a1 = fmaf(z[k+3], w1.w, a1);
            a2 = fmaf(z[k], w2.x, a2); a2 = fmaf(z[k+1], w2.y, a2); a2 = fmaf(z[k+2], w2.z, a2); a2 = fmaf(z[k+3], w2.w, a2);
            a3 = fmaf(z[k], w3.x, a3); a3 = fmaf(z[k+1], w3.y, a3); a3 = fmaf(z[k+2], w3.z, a3); a3 = fmaf(z[k+3], w3.w, a3);
        }
        f1[j+0] = fmaxf(a0, 0.f); f1[j+1] = fmaxf(a1, 0.f);
        f1[j+2] = fmaxf(a2, 0.f); f1[j+3] = fmaxf(a3, 0.f);
    }

    // feat2 = relu(fus_W2 @ feat1 + fb2)
    float f2[64];
#pragma unroll
    for (int j = 0; j < 64; j += 4) {
        float a0 = sb2[j], a1 = sb2[j+1], a2 = sb2[j+2], a3 = sb2[j+3];
#pragma unroll
        for (int k = 0; k < 64; k += 4) {
            float4 w0 = *(const float4*)(sW2 + (j+0) * 64 + k);
            float4 w1 = *(const float4*)(sW2 + (j+1) * 64 + k);
            float4 w2 = *(const float4*)(sW2 + (j+2) * 64 + k);
            float4 w3 = *(const float4*)(sW2 + (j+3) * 64 + k);
            a0 = fmaf(f1[k], w0.x, a0); a0 = fmaf(f1[k+1], w0.y, a0); a0 = fmaf(f1[k+2], w0.z, a0); a0 = fmaf(f1[k+3], w0.w, a0);
            a1 = fmaf(f1[k], w1.x, a1); a1 = fmaf(f1[k+1], w1.y, a1); a1 = fmaf(f1[k+2], w1.z, a1); a1 = fmaf(f1[k+3], w1.w, a1);
            a2 = fmaf(f1[k], w2.x, a2); a2 = fmaf(f1[k+1], w2.y, a2); a2 = fmaf(f1[k+2], w2.z, a2); a2 = fmaf(f1[k+3], w2.w, a2);
            a3 = fmaf(f1[k], w3.x, a3); a3 = fmaf(f1[k+1], w3.y, a3); a3 = fmaf(f1[k+2], w3.z, a3); a3 = fmaf(f1[k+3], w3.w, a3);
        }
        f2[j+0] = fmaxf(a0, 0.f); f2[j+1] = fmaxf(a1, 0.f);
        f2[j+2] = fmaxf(a2, 0.f); f2[j+3] = fmaxf(a3, 0.f);
    }

    // r1 = relu(res_W1 @ feat2 + rb1)
    float r1[32];
#pragma unroll
    for (int j = 0; j < 32; j += 4) {
        float a0 = srb1[j], a1 = srb1[j+1], a2 = srb1[j+2], a3 = srb1[j+3];
#pragma unroll
        for (int k = 0; k < 64; k += 4) {
            float4 w0 = *(const float4*)(sR1 + (j+0) * 64 + k);
            float4 w1 = *(const float4*)(sR1 + (j+1) * 64 + k);
            float4 w2 = *(const float4*)(sR1 + (j+2) * 64 + k);
            float4 w3 = *(const float4*)(sR1 + (j+3) * 64 + k);
            a0 = fmaf(f2[k], w0.x, a0); a0 = fmaf(f2[k+1], w0.y, a0); a0 = fmaf(f2[k+2], w0.z, a0); a0 = fmaf(f2[k+3], w0.w, a0);
            a1 = fmaf(f2[k], w1.x, a1); a1 = fmaf(f2[k+1], w1.y, a1); a1 = fmaf(f2[k+2], w1.z, a1); a1 = fmaf(f2[k+3], w1.w, a1);
            a2 = fmaf(f2[k], w2.x, a2); a2 = fmaf(f2[k+1], w2.y, a2); a2 = fmaf(f2[k+2], w2.z, a2); a2 = fmaf(f2[k+3], w2.w, a2);
            a3 = fmaf(f2[k], w3.x, a3); a3 = fmaf(f2[k+1], w3.y, a3); a3 = fmaf(f2[k+2], w3.z, a3); a3 = fmaf(f2[k+3], w3.w, a3);
        }
        r1[j+0] = fmaxf(a0, 0.f); r1[j+1] = fmaxf(a1, 0.f);
        r1[j+2] = fmaxf(a2, 0.f); r1[j+3] = fmaxf(a3, 0.f);
    }

    // r = res_W2 @ r1 + rb2
    float a0 = sscal[1], a1 = 0.f, a2 = 0.f, a3 = 0.f;
#pragma unroll
    for (int k = 0; k < 32; k += 4) {
        a0 = fmaf(r1[k+0], sR2[k+0], a0);
        a1 = fmaf(r1[k+1], sR2[k+1], a1);
        a2 = fmaf(r1[k+2], sR2[k+2], a2);
        a3 = fmaf(r1[k+3], sR2[k+3], a3);
    }
    float r = (a0 + a1) + (a2 + a3);

    float ibase = D * iphys;
    out[(size_t)0 * NPOS + idx] = ibase + r;   // I_pred
    out[(size_t)1 * NPOS + idx] = iphys;       // I_phys
    out[(size_t)2 * NPOS + idx] = ibase;       // I_base
    out[(size_t)3 * NPOS + idx] = D;           // D
    out[(size_t)4 * NPOS + idx] = r;           // r
    float* ho = out + (size_t)5 * NPOS + (size_t)idx * 8;
#pragma unroll
    for (int i = 0; i < 8; ++i) ho[i] = health[i];  // health_seq
}

// ---------------- launch ----------------------------------------------------
extern "C" void kernel_launch(void* const* d_in, const int* in_sizes, int n_in,
                              void* d_out, int out_size)
{
    const float* X        = (const float*)d_in[0];
    const int*   day_ids  = (const int*)  d_in[1];
    const float* raw      = (const float*)d_in[2];
    const float* ih0      = (const float*)d_in[3];
    const float* oW1      = (const float*)d_in[4];
    const float* ob1      = (const float*)d_in[5];
    const float* oW2      = (const float*)d_in[6];
    const float* ob2      = (const float*)d_in[7];
    const float* oW3      = (const float*)d_in[8];
    const float* ob3      = (const float*)d_in[9];
    const float* Wih0     = (const float*)d_in[10];
    const float* Whh0     = (const float*)d_in[11];
    const float* bih0     = (const float*)d_in[12];
    const float* bhh0     = (const float*)d_in[13];
    const float* Wih1     = (const float*)d_in[14];
    const float* Whh1     = (const float*)d_in[15];
    const float* bih1     = (const float*)d_in[16];
    const float* bhh1     = (const float*)d_in[17];
    const float* hdw      = (const float*)d_in[18];
    const float* hdb      = (const float*)d_in[19];
    const float* fW1      = (const float*)d_in[20];
    const float* fb1      = (const float*)d_in[21];
    const float* fW2      = (const float*)d_in[22];
    const float* fb2      = (const float*)d_in[23];
    const float* rW1      = (const float*)d_in[24];
    const float* rb1      = (const float*)d_in[25];
    const float* rW2      = (const float*)d_in[26];
    const float* rb2      = (const float*)d_in[27];

    // Layer-0 LSTM (2 rows/CTA, 128 CTAs) + ODE as CTA 128: one wave.
    k_lstm0<<<129, 256>>>(X, Wih0, Whh0, bih0, bhh0,
                          ih0, oW1, ob1, oW2, ob2, oW3, ob3);
    // Layer-1 LSTM (2 rows/CTA, 128 CTAs): one wave.
    k_lstm1<<<128, 256>>>(Wih1, Whh1, bih1, bhh1);
    // Physics + fusion MLP + all outputs.
    k_fusion<<<NPOS / 256, 256>>>(day_ids, raw, hdw, hdb,
                                  fW1, fb1, fW2, fb2,
                                  rW1, rb1, rW2, rb2,
                                  (float*)d_out);
}

// round 6
// speedup vs baseline: 1.3990x; 1.0708x over previous
#include <cuda_runtime.h>
#include <cstdint>
#include <cstddef>

#define NBATCH 256
#define NT     2048
#define NFIN   32
#define NHID   64
#define NPOS   (NBATCH * NT)   // 524288

// ---------------- scratch (static device globals: allocation-free) ----------
__device__ float g_env0[(size_t)NBATCH * NT * NHID];    // layer-0 LSTM output
__device__ float g_env1[(size_t)NBATCH * NT * NHID];    // layer-1 LSTM output
__device__ float g_gin0[(size_t)NPOS * 256];            // L0 gate input-proj
__device__ float g_gin1[(size_t)NPOS * 256];            // L1 gate input-proj
__device__ float g_traj[366 * 8];                       // ODE trajectory

// ---------------- fast activations (fp32, ~1e-6 rel err) -------------------
__device__ __forceinline__ float fsig(float x) {
    return __fdividef(1.0f, 1.0f + __expf(-x));
}
__device__ __forceinline__ float ftanh(float x) {
    float ax = fabsf(x);
    float e  = __expf(-2.0f * ax);
    float r  = __fdividef(1.0f - e, 1.0f + e);
    return copysignf(r, x);
}

// ---------------- ODE body (runs as blockIdx == 128 of k_rec0) -------------
__device__ void ode_body(int tid,
                         const float* __restrict__ h0,
                         const float* __restrict__ W1, const float* __restrict__ b1,
                         const float* __restrict__ W2, const float* __restrict__ b2,
                         const float* __restrict__ W3, const float* __restrict__ b3)
{
    __shared__ float sInp[12];
    __shared__ float sz1[64];
    __shared__ float sz2[64];
    __shared__ float sk[6][8];
    __shared__ float shh[8];
    __shared__ __align__(16) float sW3[8 * 64];
    __shared__ float sb3[8];

    float w1r[9];
    float w2r[64];
    float b1j = 0.f, b2j = 0.f;
    if (tid < 64) {
#pragma unroll
        for (int k = 0; k < 9; ++k) w1r[k] = W1[tid * 9 + k];
#pragma unroll
        for (int k = 0; k < 64; ++k) w2r[k] = W2[tid * 64 + k];
        b1j = b1[tid];
        b2j = b2[tid];
    }
    for (int i = tid; i < 8 * 64; i += 256) sW3[i] = W3[i];
    if (tid < 8) {
        sb3[tid] = b3[tid];
        shh[tid] = h0[tid];
        g_traj[tid] = h0[tid];
    }
    __syncthreads();

    const float dt = 1.0f / 365.0f;

    for (int d = 0; d < 365; ++d) {
        float t0 = (float)d * dt;
#pragma unroll 1
        for (int s = 0; s < 6; ++s) {
            if (tid < 8) {
                float v = shh[tid];
                if (s == 1) v += dt * (0.2f * sk[0][tid]);
                else if (s == 2) v += dt * ((3.f/40.f)*sk[0][tid] + (9.f/40.f)*sk[1][tid]);
                else if (s == 3) v += dt * ((44.f/45.f)*sk[0][tid] - (56.f/15.f)*sk[1][tid] + (32.f/9.f)*sk[2][tid]);
                else if (s == 4) v += dt * ((19372.f/6561.f)*sk[0][tid] - (25360.f/2187.f)*sk[1][tid]
                                          + (64448.f/6561.f)*sk[2][tid] - (212.f/729.f)*sk[3][tid]);
                else if (s == 5) v += dt * ((9017.f/3168.f)*sk[0][tid] - (355.f/33.f)*sk[1][tid]
                                          + (46732.f/5247.f)*sk[2][tid] + (49.f/176.f)*sk[3][tid]
                                          - (5103.f/18656.f)*sk[4][tid]);
                sInp[tid] = v;
            }
            if (tid == 8) {
                float cn;
                if (s == 0) cn = 0.0f;
                else if (s == 1) cn = 0.2f;
                else if (s == 2) cn = 0.3f;
                else if (s == 3) cn = 0.8f;
                else if (s == 4) cn = 8.f/9.f;
                else cn = 1.0f;
                sInp[8] = t0 + cn * dt;
            }
            __syncthreads();
            if (tid < 64) {
                float a = b1j;
#pragma unroll
                for (int k = 0; k < 9; ++k) a = fmaf(w1r[k], sInp[k], a);
                sz1[tid] = ftanh(a);
            }
            __syncthreads();
            if (tid < 64) {
                float a0 = b2j, a1 = 0.f, a2 = 0.f, a3 = 0.f;
#pragma unroll
                for (int k = 0; k < 64; k += 4) {
                    a0 = fmaf(w2r[k+0], sz1[k+0], a0);
                    a1 = fmaf(w2r[k+1], sz1[k+1], a1);
                    a2 = fmaf(w2r[k+2], sz1[k+2], a2);
                    a3 = fmaf(w2r[k+3], sz1[k+3], a3);
                }
                sz2[tid] = ftanh((a0 + a1) + (a2 + a3));
            }
            __syncthreads();
            if (tid < 8) {
                float a0 = sb3[tid], a1 = 0.f, a2 = 0.f, a3 = 0.f;
#pragma unroll
                for (int k = 0; k < 64; k += 4) {
                    a0 = fmaf(sW3[tid*64 + k+0], sz2[k+0], a0);
                    a1 = fmaf(sW3[tid*64 + k+1], sz2[k+1], a1);
                    a2 = fmaf(sW3[tid*64 + k+2], sz2[k+2], a2);
                    a3 = fmaf(sW3[tid*64 + k+3], sz2[k+3], a3);
                }
                sk[s][tid] = (a0 + a1) + (a2 + a3);
            }
            __syncthreads();
        }
        if (tid < 8) {
            float hn = shh[tid] + dt * ((35.f/384.f)   * sk[0][tid]
                                      + (500.f/1113.f) * sk[2][tid]
                                      + (125.f/192.f)  * sk[3][tid]
                                      - (2187.f/6784.f)* sk[4][tid]
                                      + (11.f/84.f)    * sk[5][tid]);
            shh[tid] = hn;
            g_traj[(d + 1) * 8 + tid] = hn;
        }
        __syncthreads();
    }
}

// ============================================================================
// Gate input-projection GEMMs (embarrassingly parallel).
// gin[pos][r] = sum_k W[r][k] * x[pos][k] + (bih[r]+bhh[r])
// CTA = 128 positions, thread = one gate row (weights in regs), x in smem.
// ============================================================================
__global__ __launch_bounds__(256) void k_gates0(
    const float* __restrict__ X,
    const float* __restrict__ Wih,
    const float* __restrict__ bih, const float* __restrict__ bhh,
    float* __restrict__ gout)
{
    __shared__ __align__(16) float xs[128 * NFIN];      // 16 kB
    const int tid = threadIdx.x;
    const size_t pos0 = (size_t)blockIdx.x * 128;

    const float4* xg = (const float4*)(X + pos0 * NFIN);
    float4* xs4 = (float4*)xs;
#pragma unroll
    for (int i = 0; i < 4; ++i) xs4[tid + 256 * i] = xg[tid + 256 * i];

    float wr[NFIN];
#pragma unroll
    for (int k = 0; k < NFIN; ++k) wr[k] = Wih[tid * NFIN + k];
    const float bias = bih[tid] + bhh[tid];
    __syncthreads();

#pragma unroll 1
    for (int p = 0; p < 128; p += 4) {
        float a0 = bias, a1 = bias, a2 = bias, a3 = bias;
#pragma unroll
        for (int k = 0; k < NFIN; k += 4) {
            float4 v0 = *(const float4*)(xs + (p+0) * NFIN + k);
            float4 v1 = *(const float4*)(xs + (p+1) * NFIN + k);
            float4 v2 = *(const float4*)(xs + (p+2) * NFIN + k);
            float4 v3 = *(const float4*)(xs + (p+3) * NFIN + k);
            a0 = fmaf(wr[k],   v0.x, a0); a0 = fmaf(wr[k+1], v0.y, a0);
            a0 = fmaf(wr[k+2], v0.z, a0); a0 = fmaf(wr[k+3], v0.w, a0);
            a1 = fmaf(wr[k],   v1.x, a1); a1 = fmaf(wr[k+1], v1.y, a1);
            a1 = fmaf(wr[k+2], v1.z, a1); a1 = fmaf(wr[k+3], v1.w, a1);
            a2 = fmaf(wr[k],   v2.x, a2); a2 = fmaf(wr[k+1], v2.y, a2);
            a2 = fmaf(wr[k+2], v2.z, a2); a2 = fmaf(wr[k+3], v2.w, a2);
            a3 = fmaf(wr[k],   v3.x, a3); a3 = fmaf(wr[k+1], v3.y, a3);
            a3 = fmaf(wr[k+2], v3.z, a3); a3 = fmaf(wr[k+3], v3.w, a3);
        }
        gout[(pos0 + p + 0) * 256 + tid] = a0;
        gout[(pos0 + p + 1) * 256 + tid] = a1;
        gout[(pos0 + p + 2) * 256 + tid] = a2;
        gout[(pos0 + p + 3) * 256 + tid] = a3;
    }
}

__global__ __launch_bounds__(256) void k_gates1(
    const float* __restrict__ Wih,
    const float* __restrict__ bih, const float* __restrict__ bhh,
    float* __restrict__ gout)
{
    __shared__ __align__(16) float xs[128 * NHID];      // 32 kB
    const int tid = threadIdx.x;
    const size_t pos0 = (size_t)blockIdx.x * 128;

    const float4* xg = (const float4*)(g_env0 + pos0 * NHID);
    float4* xs4 = (float4*)xs;
#pragma unroll
    for (int i = 0; i < 8; ++i) xs4[tid + 256 * i] = xg[tid + 256 * i];

    float wr[NHID];
#pragma unroll
    for (int k = 0; k < NHID; ++k) wr[k] = Wih[tid * NHID + k];
    const float bias = bih[tid] + bhh[tid];
    __syncthreads();

#pragma unroll 1
    for (int p = 0; p < 128; p += 4) {
        float a0 = bias, a1 = bias, a2 = bias, a3 = bias;
#pragma unroll
        for (int k = 0; k < NHID; k += 4) {
            float4 v0 = *(const float4*)(xs + (p+0) * NHID + k);
            float4 v1 = *(const float4*)(xs + (p+1) * NHID + k);
            float4 v2 = *(const float4*)(xs + (p+2) * NHID + k);
            float4 v3 = *(const float4*)(xs + (p+3) * NHID + k);
            a0 = fmaf(wr[k],   v0.x, a0); a0 = fmaf(wr[k+1], v0.y, a0);
            a0 = fmaf(wr[k+2], v0.z, a0); a0 = fmaf(wr[k+3], v0.w, a0);
            a1 = fmaf(wr[k],   v1.x, a1); a1 = fmaf(wr[k+1], v1.y, a1);
            a1 = fmaf(wr[k+2], v1.z, a1); a1 = fmaf(wr[k+3], v1.w, a1);
            a2 = fmaf(wr[k],   v2.x, a2); a2 = fmaf(wr[k+1], v2.y, a2);
            a2 = fmaf(wr[k+2], v2.z, a2); a2 = fmaf(wr[k+3], v2.w, a2);
            a3 = fmaf(wr[k],   v3.x, a3); a3 = fmaf(wr[k+1], v3.y, a3);
            a3 = fmaf(wr[k+2], v3.z, a3); a3 = fmaf(wr[k+3], v3.w, a3);
        }
        gout[(pos0 + p + 0) * 256 + tid] = a0;
        gout[(pos0 + p + 1) * 256 + tid] = a1;
        gout[(pos0 + p + 2) * 256 + tid] = a2;
        gout[(pos0 + p + 3) * 256 + tid] = a3;
    }
}

// ============================================================================
// Recurrent-only LSTM step kernel: gate = gin[s] + Whh.h(s-1).
// 2 batch rows per CTA, 256 threads; thread -> (gate gt, unit u):
// gt = l>>3, u = (w<<3)|(l&7), weight row r = gt*64+u in regs (64 floats).
// Cell update in-warp via shfl; hs ping-pong; 1 barrier/step; gin prefetched
// 2 steps ahead in registers (LDG latency cover).
// ============================================================================
__device__ __forceinline__ void rec_body(
    const float* __restrict__ gin, const float* __restrict__ Whh,
    float* __restrict__ eout)
{
    const int t = threadIdx.x;
    const int w  = t >> 5, l = t & 31;
    const int gt = l >> 3;
    const int u  = (w << 3) | (l & 7);
    const int r  = gt * 64 + u;
    const int lb = l & 7;

    float whh[NHID];
#pragma unroll
    for (int k = 0; k < NHID; ++k) whh[k] = Whh[r * NHID + k];

    __shared__ __align__(16) float hs[2][2][NHID];
    if (t < 128) hs[0][t >> 6][t & 63] = 0.0f;

    const int b0 = blockIdx.x * 2;
    const float* gA = gin + (size_t)b0 * NT * 256;
    const float* gB = gA + (size_t)NT * 256;
    float* e0 = eout + (size_t)b0 * NT * NHID;
    float* e1 = e0 + (size_t)NT * NHID;
    const bool isg = (gt == 2);

    float cA = 0.0f, cB = 0.0f;
    float pA0 = gA[r],        pB0 = gB[r];
    float pA1 = gA[256 + r],  pB1 = gB[256 + r];
    __syncthreads();

#define REC_STEP(S, PA, PB)                                                    \
    {                                                                          \
        const int cur = (S) & 1;                                               \
        float npA = 0.f, npB = 0.f;                                            \
        if ((S) + 2 < NT) {                                                    \
            npA = gA[(size_t)((S) + 2) * 256 + r];                             \
            npB = gB[(size_t)((S) + 2) * 256 + r];                             \
        }                                                                      \
        float aA0 = (PA), aA1 = 0.f, aA2 = 0.f, aA3 = 0.f;                     \
        float aB0 = (PB), aB1 = 0.f, aB2 = 0.f, aB3 = 0.f;                     \
        _Pragma("unroll")                                                      \
        for (int k = 0; k < NHID; k += 4) {                                    \
            float4 vA = *(const float4*)(hs[cur][0] + k);                      \
            float4 vB = *(const float4*)(hs[cur][1] + k);                      \
            aA0 = fmaf(whh[k+0], vA.x, aA0);  aB0 = fmaf(whh[k+0], vB.x, aB0); \
            aA1 = fmaf(whh[k+1], vA.y, aA1);  aB1 = fmaf(whh[k+1], vB.y, aB1); \
            aA2 = fmaf(whh[k+2], vA.z, aA2);  aB2 = fmaf(whh[k+2], vB.z, aB2); \
            aA3 = fmaf(whh[k+3], vA.w, aA3);  aB3 = fmaf(whh[k+3], vB.w, aB3); \
        }                                                                      \
        float ppA = (aA0 + aA1) + (aA2 + aA3);                                 \
        float ppB = (aB0 + aB1) + (aB2 + aB3);                                 \
        float actA = isg ? ftanh(ppA) : fsig(ppA);                             \
        float actB = isg ? ftanh(ppB) : fsig(ppB);                             \
        float iA = __shfl_sync(0xffffffffu, actA, lb);                         \
        float fA = __shfl_sync(0xffffffffu, actA, lb + 8);                     \
        float gA_ = __shfl_sync(0xffffffffu, actA, lb + 16);                   \
        float oA = __shfl_sync(0xffffffffu, actA, lb + 24);                    \
        float iB = __shfl_sync(0xffffffffu, actB, lb);                         \
        float fB = __shfl_sync(0xffffffffu, actB, lb + 8);                     \
        float gB_ = __shfl_sync(0xffffffffu, actB, lb + 16);                   \
        float oB = __shfl_sync(0xffffffffu, actB, lb + 24);                    \
        cA = fA * cA + iA * gA_;                                               \
        cB = fB * cB + iB * gB_;                                               \
        float hA = oA * ftanh(cA);                                             \
        float hB = oB * ftanh(cB);                                             \
        if (gt == 0) {                                                         \
            hs[cur ^ 1][0][u] = hA;                                            \
            hs[cur ^ 1][1][u] = hB;                                            \
            e0[(size_t)(S) * NHID + u] = hA;                                   \
            e1[(size_t)(S) * NHID + u] = hB;                                   \
        }                                                                      \
        (PA) = npA; (PB) = npB;                                                \
        __syncthreads();                                                       \
    }

#pragma unroll 1
    for (int s = 0; s < NT; s += 2) {
        REC_STEP(s,     pA0, pB0)
        REC_STEP(s + 1, pA1, pB1)
    }
#undef REC_STEP
}

__global__ __launch_bounds__(256, 1) void k_rec0(
    const float* __restrict__ Whh,
    const float* __restrict__ h0,
    const float* __restrict__ oW1, const float* __restrict__ ob1,
    const float* __restrict__ oW2, const float* __restrict__ ob2,
    const float* __restrict__ oW3, const float* __restrict__ ob3)
{
    if (blockIdx.x == 128) {
        ode_body(threadIdx.x, h0, oW1, ob1, oW2, ob2, oW3, ob3);
        return;
    }
    rec_body(g_gin0, Whh, g_env0);
}

__global__ __launch_bounds__(256, 1) void k_rec1(
    const float* __restrict__ Whh)
{
    rec_body(g_gin1, Whh, g_env1);
}

// ---------------- Kernel C: physics + fusion MLP + outputs ------------------
__global__ __launch_bounds__(256) void k_fusion(
    const int*   __restrict__ day_ids,
    const float* __restrict__ raw,
    const float* __restrict__ hdw, const float* __restrict__ hdb,
    const float* __restrict__ fW1, const float* __restrict__ fb1,
    const float* __restrict__ fW2, const float* __restrict__ fb2,
    const float* __restrict__ rW1, const float* __restrict__ rb1,
    const float* __restrict__ rW2, const float* __restrict__ rb2,
    float* __restrict__ out)
{
    const int tid = threadIdx.x;

    __shared__ __align__(16) float sW1[64 * 76];   // fus_W1 padded 73 -> 76
    __shared__ __align__(16) float sW2[64 * 64];
    __shared__ __align__(16) float sR1[32 * 64];
    __shared__ float sR2[32];
    __shared__ float sb1[64], sb2[64], srb1[32];
    __shared__ float shdw[8];
    __shared__ float sscal[2];

    for (int i = tid; i < 64 * 76; i += 256) {
        int j = i / 76, k = i - j * 76;
        sW1[i] = (k < 73) ? fW1[j * 73 + k] : 0.0f;
    }
    for (int i = tid; i < 64 * 64; i += 256) sW2[i] = fW2[i];
    for (int i = tid; i < 32 * 64; i += 256) sR1[i] = rW1[i];
    if (tid < 64) { sb1[tid] = fb1[tid]; sb2[tid] = fb2[tid]; }
    if (tid < 32) { sR2[tid] = rW2[tid]; srb1[tid] = rb1[tid]; }
    if (tid < 8)  shdw[tid] = hdw[tid];
    if (tid == 0) { sscal[0] = hdb[0]; sscal[1] = rb2[0]; }
    __syncthreads();

    const int idx = blockIdx.x * 256 + tid;       // grid = 2048 -> idx < NPOS
    const int b = idx >> 11;

    float z[76];
    const float4* ep = (const float4*)(g_env1 + (size_t)idx * NHID);
#pragma unroll
    for (int i = 0; i < 16; ++i) {
        float4 v = ep[i];
        z[4*i+0] = v.x; z[4*i+1] = v.y; z[4*i+2] = v.z; z[4*i+3] = v.w;
    }
    const int day = day_ids[b];
    float health[8];
#pragma unroll
    for (int i = 0; i < 8; ++i) { health[i] = g_traj[day * 8 + i]; z[64 + i] = health[i]; }

    float4 rv = ((const float4*)raw)[idx];
    float iphys = rv.x * 9.0f * (1.0f + 0.0005f * (rv.y - 0.5f));
    z[72] = iphys; z[73] = 0.f; z[74] = 0.f; z[75] = 0.f;

    float rawD = sscal[0];
#pragma unroll
    for (int i = 0; i < 8; ++i) rawD = fmaf(health[i], shdw[i], rawD);
    float D = fsig(rawD);

    // feat1 = relu(fus_W1 @ z + fb1)
    float f1[64];
#pragma unroll
    for (int j = 0; j < 64; j += 4) {
        float a0 = sb1[j], a1 = sb1[j+1], a2 = sb1[j+2], a3 = sb1[j+3];
#pragma unroll
        for (int k = 0; k < 76; k += 4) {
            float4 w0 = *(const float4*)(sW1 + (j+0) * 76 + k);
            float4 w1 = *(const float4*)(sW1 + (j+1) * 76 + k);
            float4 w2 = *(const float4*)(sW1 + (j+2) * 76 + k);
            float4 w3 = *(const float4*)(sW1 + (j+3) * 76 + k);
            a0 = fmaf(z[k], w0.x, a0); a0 = fmaf(z[k+1], w0.y, a0); a0 = fmaf(z[k+2], w0.z, a0); a0 = fmaf(z[k+3], w0.w, a0);
            a1 = fmaf(z[k], w1.x, a1); a1 = fmaf(z[k+1], w1.y, a1); a1 = fmaf(z[k+2], w1.z, a1); a1 = fmaf(z[k+3], w1.w, a1);
            a2 = fmaf(z[k], w2.x, a2); a2 = fmaf(z[k+1], w2.y, a2); a2 = fmaf(z[k+2], w2.z, a2); a2 = fmaf(z[k+3], w2.w, a2);
            a3 = fmaf(z[k], w3.x, a3); a3 = fmaf(z[k+1], w3.y, a3); a3 = fmaf(z[k+2], w3.z, a3); a3 = fmaf(z[k+3], w3.w, a3);
        }
        f1[j+0] = fmaxf(a0, 0.f); f1[j+1] = fmaxf(a1, 0.f);
        f1[j+2] = fmaxf(a2, 0.f); f1[j+3] = fmaxf(a3, 0.f);
    }

    // feat2 = relu(fus_W2 @ feat1 + fb2)
    float f2[64];
#pragma unroll
    for (int j = 0; j < 64; j += 4) {
        float a0 = sb2[j], a1 = sb2[j+1], a2 = sb2[j+2], a3 = sb2[j+3];
#pragma unroll
        for (int k = 0; k < 64; k += 4) {
            float4 w0 = *(const float4*)(sW2 + (j+0) * 64 + k);
            float4 w1 = *(const float4*)(sW2 + (j+1) * 64 + k);
            float4 w2 = *(const float4*)(sW2 + (j+2) * 64 + k);
            float4 w3 = *(const float4*)(sW2 + (j+3) * 64 + k);
            a0 = fmaf(f1[k], w0.x, a0); a0 = fmaf(f1[k+1], w0.y, a0); a0 = fmaf(f1[k+2], w0.z, a0); a0 = fmaf(f1[k+3], w0.w, a0);
            a1 = fmaf(f1[k], w1.x, a1); a1 = fmaf(f1[k+1], w1.y, a1); a1 = fmaf(f1[k+2], w1.z, a1); a1 = fmaf(f1[k+3], w1.w, a1);
            a2 = fmaf(f1[k], w2.x, a2); a2 = fmaf(f1[k+1], w2.y, a2); a2 = fmaf(f1[k+2], w2.z, a2); a2 = fmaf(f1[k+3], w2.w, a2);
            a3 = fmaf(f1[k], w3.x, a3); a3 = fmaf(f1[k+1], w3.y, a3); a3 = fmaf(f1[k+2], w3.z, a3); a3 = fmaf(f1[k+3], w3.w, a3);
        }
        f2[j+0] = fmaxf(a0, 0.f); f2[j+1] = fmaxf(a1, 0.f);
        f2[j+2] = fmaxf(a2, 0.f); f2[j+3] = fmaxf(a3, 0.f);
    }

    // r1 = relu(res_W1 @ feat2 + rb1)
    float r1[32];
#pragma unroll
    for (int j = 0; j < 32; j += 4) {
        float a0 = srb1[j], a1 = srb1[j+1], a2 = srb1[j+2], a3 = srb1[j+3];
#pragma unroll
        for (int k = 0; k < 64; k += 4) {
            float4 w0 = *(const float4*)(sR1 + (j+0) * 64 + k);
            float4 w1 = *(const float4*)(sR1 + (j+1) * 64 + k);
            float4 w2 = *(const float4*)(sR1 + (j+2) * 64 + k);
            float4 w3 = *(const float4*)(sR1 + (j+3) * 64 + k);
            a0 = fmaf(f2[k], w0.x, a0); a0 = fmaf(f2[k+1], w0.y, a0); a0 = fmaf(f2[k+2], w0.z, a0); a0 = fmaf(f2[k+3], w0.w, a0);
            a1 = fmaf(f2[k], w1.x, a1); a1 = fmaf(f2[k+1], w1.y, a1); a1 = fmaf(f2[k+2], w1.z, a1); a1 = fmaf(f2[k+3], w1.w, a1);
            a2 = fmaf(f2[k], w2.x, a2); a2 = fmaf(f2[k+1], w2.y, a2); a2 = fmaf(f2[k+2], w2.z, a2); a2 = fmaf(f2[k+3], w2.w, a2);
            a3 = fmaf(f2[k], w3.x, a3); a3 = fmaf(f2[k+1], w3.y, a3); a3 = fmaf(f2[k+2], w3.z, a3); a3 = fmaf(f2[k+3], w3.w, a3);
        }
        r1[j+0] = fmaxf(a0, 0.f); r1[j+1] = fmaxf(a1, 0.f);
        r1[j+2] = fmaxf(a2, 0.f); r1[j+3] = fmaxf(a3, 0.f);
    }

    // r = res_W2 @ r1 + rb2
    float a0 = sscal[1], a1 = 0.f, a2 = 0.f, a3 = 0.f;
#pragma unroll
    for (int k = 0; k < 32; k += 4) {
        a0 = fmaf(r1[k+0], sR2[k+0], a0);
        a1 = fmaf(r1[k+1], sR2[k+1], a1);
        a2 = fmaf(r1[k+2], sR2[k+2], a2);
        a3 = fmaf(r1[k+3], sR2[k+3], a3);
    }
    float r = (a0 + a1) + (a2 + a3);

    float ibase = D * iphys;
    out[(size_t)0 * NPOS + idx] = ibase + r;   // I_pred
    out[(size_t)1 * NPOS + idx] = iphys;       // I_phys
    out[(size_t)2 * NPOS + idx] = ibase;       // I_base
    out[(size_t)3 * NPOS + idx] = D;           // D
    out[(size_t)4 * NPOS + idx] = r;           // r
    float* ho = out + (size_t)5 * NPOS + (size_t)idx * 8;
#pragma unroll
    for (int i = 0; i < 8; ++i) ho[i] = health[i];  // health_seq
}

// ---------------- launch ----------------------------------------------------
extern "C" void kernel_launch(void* const* d_in, const int* in_sizes, int n_in,
                              void* d_out, int out_size)
{
    const float* X        = (const float*)d_in[0];
    const int*   day_ids  = (const int*)  d_in[1];
    const float* raw      = (const float*)d_in[2];
    const float* ih0      = (const float*)d_in[3];
    const float* oW1      = (const float*)d_in[4];
    const float* ob1      = (const float*)d_in[5];
    const float* oW2      = (const float*)d_in[6];
    const float* ob2      = (const float*)d_in[7];
    const float* oW3      = (const float*)d_in[8];
    const float* ob3      = (const float*)d_in[9];
    const float* Wih0     = (const float*)d_in[10];
    const float* Whh0     = (const float*)d_in[11];
    const float* bih0     = (const float*)d_in[12];
    const float* bhh0     = (const float*)d_in[13];
    const float* Wih1     = (const float*)d_in[14];
    const float* Whh1     = (const float*)d_in[15];
    const float* bih1     = (const float*)d_in[16];
    const float* bhh1     = (const float*)d_in[17];
    const float* hdw      = (const float*)d_in[18];
    const float* hdb      = (const float*)d_in[19];
    const float* fW1      = (const float*)d_in[20];
    const float* fb1      = (const float*)d_in[21];
    const float* fW2      = (const float*)d_in[22];
    const float* fb2      = (const float*)d_in[23];
    const float* rW1      = (const float*)d_in[24];
    const float* rb1      = (const float*)d_in[25];
    const float* rW2      = (const float*)d_in[26];
    const float* rb2      = (const float*)d_in[27];

    float* gin0;  cudaGetSymbolAddress((void**)&gin0, g_gin0);
    float* gin1;  cudaGetSymbolAddress((void**)&gin1, g_gin1);

    // L0 input projection (parallel GEMM).
    k_gates0<<<NPOS / 128, 256>>>(X, Wih0, bih0, bhh0, gin0);
    // L0 recurrence (+ ODE hidden as CTA 128): one wave.
    k_rec0<<<129, 256>>>(Whh0, ih0, oW1, ob1, oW2, ob2, oW3, ob3);
    // L1 input projection (parallel GEMM on env0).
    k_gates1<<<NPOS / 128, 256>>>(Wih1, bih1, bhh1, gin1);
    // L1 recurrence: one wave.
    k_rec1<<<128, 256>>>(Whh1);
    // Physics + fusion MLP + all outputs.
    k_fusion<<<NPOS / 256, 256>>>(day_ids, raw, hdw, hdb,
                                  fW1, fb1, fW2, fb2,
                                  rW1, rb1, rW2, rb2,
                                  (float*)d_out);
}

// round 7
// speedup vs baseline: 2.0212x; 1.4448x over previous
#include <cuda_runtime.h>
#include <cstdint>
#include <cstddef>

#define NBATCH 256
#define NT     2048
#define NFIN   32
#define NHID   64
#define NPOS   (NBATCH * NT)   // 524288

typedef unsigned long long u64;

// ---------------- scratch (static device globals: allocation-free) ----------
__device__ float g_env1[(size_t)NBATCH * NT * NHID];    // layer-1 LSTM output
__device__ float g_gin0[(size_t)NPOS * 256];            // L0 gate input-proj
__device__ float g_traj[366 * 8];                       // ODE trajectory

// ---------------- fast activations (fp32, ~1e-6 rel err) -------------------
__device__ __forceinline__ float fsig(float x) {
    return __fdividef(1.0f, 1.0f + __expf(-x));
}
__device__ __forceinline__ float ftanh(float x) {
    float ax = fabsf(x);
    float e  = __expf(-2.0f * ax);
    float r  = __fdividef(1.0f - e, 1.0f + e);
    return copysignf(r, x);
}

// ---------------- packed f32x2 helpers --------------------------------------
__device__ __forceinline__ u64 pack2(float lo, float hi) {
    u64 r; asm("mov.b64 %0, {%1, %2};" : "=l"(r) : "f"(lo), "f"(hi)); return r;
}
__device__ __forceinline__ void fma2(u64& a, u64 w, u64 v) {
    asm("fma.rn.f32x2 %0, %1, %2, %0;" : "+l"(a) : "l"(w), "l"(v));
}
__device__ __forceinline__ float hsum2(u64 a) {
    float lo, hi; asm("mov.b64 {%0, %1}, %2;" : "=f"(lo), "=f"(hi) : "l"(a));
    return lo + hi;
}

// ---------------- ODE body (runs as blockIdx == 128 of fused rec) ----------
__device__ void ode_body(int tid,
                         const float* __restrict__ h0,
                         const float* __restrict__ W1, const float* __restrict__ b1,
                         const float* __restrict__ W2, const float* __restrict__ b2,
                         const float* __restrict__ W3, const float* __restrict__ b3)
{
    __shared__ float sInp[12];
    __shared__ float sz1[64];
    __shared__ float sz2[64];
    __shared__ float sk[6][8];
    __shared__ float shh[8];
    __shared__ __align__(16) float sW3[8 * 64];
    __shared__ float sb3[8];

    float w1r[9];
    float w2r[64];
    float b1j = 0.f, b2j = 0.f;
    if (tid < 64) {
#pragma unroll
        for (int k = 0; k < 9; ++k) w1r[k] = W1[tid * 9 + k];
#pragma unroll
        for (int k = 0; k < 64; ++k) w2r[k] = W2[tid * 64 + k];
        b1j = b1[tid];
        b2j = b2[tid];
    }
    for (int i = tid; i < 8 * 64; i += 256) sW3[i] = W3[i];
    if (tid < 8) {
        sb3[tid] = b3[tid];
        shh[tid] = h0[tid];
        g_traj[tid] = h0[tid];
    }
    __syncthreads();

    const float dt = 1.0f / 365.0f;

    for (int d = 0; d < 365; ++d) {
        float t0 = (float)d * dt;
#pragma unroll 1
        for (int s = 0; s < 6; ++s) {
            if (tid < 8) {
                float v = shh[tid];
                if (s == 1) v += dt * (0.2f * sk[0][tid]);
                else if (s == 2) v += dt * ((3.f/40.f)*sk[0][tid] + (9.f/40.f)*sk[1][tid]);
                else if (s == 3) v += dt * ((44.f/45.f)*sk[0][tid] - (56.f/15.f)*sk[1][tid] + (32.f/9.f)*sk[2][tid]);
                else if (s == 4) v += dt * ((19372.f/6561.f)*sk[0][tid] - (25360.f/2187.f)*sk[1][tid]
                                          + (64448.f/6561.f)*sk[2][tid] - (212.f/729.f)*sk[3][tid]);
                else if (s == 5) v += dt * ((9017.f/3168.f)*sk[0][tid] - (355.f/33.f)*sk[1][tid]
                                          + (46732.f/5247.f)*sk[2][tid] + (49.f/176.f)*sk[3][tid]
                                          - (5103.f/18656.f)*sk[4][tid]);
                sInp[tid] = v;
            }
            if (tid == 8) {
                float cn;
                if (s == 0) cn = 0.0f;
                else if (s == 1) cn = 0.2f;
                else if (s == 2) cn = 0.3f;
                else if (s == 3) cn = 0.8f;
                else if (s == 4) cn = 8.f/9.f;
                else cn = 1.0f;
                sInp[8] = t0 + cn * dt;
            }
            __syncthreads();
            if (tid < 64) {
                float a = b1j;
#pragma unroll
                for (int k = 0; k < 9; ++k) a = fmaf(w1r[k], sInp[k], a);
                sz1[tid] = ftanh(a);
            }
            __syncthreads();
            if (tid < 64) {
                float a0 = b2j, a1 = 0.f, a2 = 0.f, a3 = 0.f;
#pragma unroll
                for (int k = 0; k < 64; k += 4) {
                    a0 = fmaf(w2r[k+0], sz1[k+0], a0);
                    a1 = fmaf(w2r[k+1], sz1[k+1], a1);
                    a2 = fmaf(w2r[k+2], sz1[k+2], a2);
                    a3 = fmaf(w2r[k+3], sz1[k+3], a3);
                }
                sz2[tid] = ftanh((a0 + a1) + (a2 + a3));
            }
            __syncthreads();
            if (tid < 8) {
                float a0 = sb3[tid], a1 = 0.f, a2 = 0.f, a3 = 0.f;
#pragma unroll
                for (int k = 0; k < 64; k += 4) {
                    a0 = fmaf(sW3[tid*64 + k+0], sz2[k+0], a0);
                    a1 = fmaf(sW3[tid*64 + k+1], sz2[k+1], a1);
                    a2 = fmaf(sW3[tid*64 + k+2], sz2[k+2], a2);
                    a3 = fmaf(sW3[tid*64 + k+3], sz2[k+3], a3);
                }
                sk[s][tid] = (a0 + a1) + (a2 + a3);
            }
            __syncthreads();
        }
        if (tid < 8) {
            float hn = shh[tid] + dt * ((35.f/384.f)   * sk[0][tid]
                                      + (500.f/1113.f) * sk[2][tid]
                                      + (125.f/192.f)  * sk[3][tid]
                                      - (2187.f/6784.f)* sk[4][tid]
                                      + (11.f/84.f)    * sk[5][tid]);
            shh[tid] = hn;
            g_traj[(d + 1) * 8 + tid] = hn;
        }
        __syncthreads();
    }
}

// ============================================================================
// L0 gate input-projection GEMM (embarrassingly parallel).
// gin[pos][r] = sum_k Wih0[r][k] * x[pos][k] + (bih[r]+bhh[r])
// ============================================================================
__global__ __launch_bounds__(256) void k_gates0(
    const float* __restrict__ X,
    const float* __restrict__ Wih,
    const float* __restrict__ bih, const float* __restrict__ bhh,
    float* __restrict__ gout)
{
    __shared__ __align__(16) float xs[128 * NFIN];      // 16 kB
    const int tid = threadIdx.x;
    const size_t pos0 = (size_t)blockIdx.x * 128;

    const float4* xg = (const float4*)(X + pos0 * NFIN);
    float4* xs4 = (float4*)xs;
#pragma unroll
    for (int i = 0; i < 4; ++i) xs4[tid + 256 * i] = xg[tid + 256 * i];

    float wr[NFIN];
#pragma unroll
    for (int k = 0; k < NFIN; ++k) wr[k] = Wih[tid * NFIN + k];
    const float bias = bih[tid] + bhh[tid];
    __syncthreads();

#pragma unroll 1
    for (int p = 0; p < 128; p += 4) {
        float a0 = bias, a1 = bias, a2 = bias, a3 = bias;
#pragma unroll
        for (int k = 0; k < NFIN; k += 4) {
            float4 v0 = *(const float4*)(xs + (p+0) * NFIN + k);
            float4 v1 = *(const float4*)(xs + (p+1) * NFIN + k);
            float4 v2 = *(const float4*)(xs + (p+2) * NFIN + k);
            float4 v3 = *(const float4*)(xs + (p+3) * NFIN + k);
            a0 = fmaf(wr[k],   v0.x, a0); a0 = fmaf(wr[k+1], v0.y, a0);
            a0 = fmaf(wr[k+2], v0.z, a0); a0 = fmaf(wr[k+3], v0.w, a0);
            a1 = fmaf(wr[k],   v1.x, a1); a1 = fmaf(wr[k+1], v1.y, a1);
            a1 = fmaf(wr[k+2], v1.z, a1); a1 = fmaf(wr[k+3], v1.w, a1);
            a2 = fmaf(wr[k],   v2.x, a2); a2 = fmaf(wr[k+1], v2.y, a2);
            a2 = fmaf(wr[k+2], v2.z, a2); a2 = fmaf(wr[k+3], v2.w, a2);
            a3 = fmaf(wr[k],   v3.x, a3); a3 = fmaf(wr[k+1], v3.y, a3);
            a3 = fmaf(wr[k+2], v3.z, a3); a3 = fmaf(wr[k+3], v3.w, a3);
        }
        gout[(pos0 + p + 0) * 256 + tid] = a0;
        gout[(pos0 + p + 1) * 256 + tid] = a1;
        gout[(pos0 + p + 2) * 256 + tid] = a2;
        gout[(pos0 + p + 3) * 256 + tid] = a3;
    }
}

// ============================================================================
// Fused recurrence: L0 + L1 with 1-step skew, f32x2 packed FMA dots.
// 2 batch rows per CTA, 128 CTAs (+ ODE at blockIdx 128): one wave.
// Thread -> (gate gt, unit u): gt = l>>3, u = (w<<3)|(l&7), r = gt*64+u.
// Weights (Whh0, Wih1, Whh1 row r) pre-packed as u64 pairs in registers.
// At iteration s: L0 computes step s (gin0[s] + Whh0 h0[s-1]);
//                 L1 computes step s-1 (Wih1 h0[s-1] + Whh1 h1[s-2] + bias1).
// Cell updates in-warp via shfl; hs0/hs1 ping-pong; one barrier per step.
// ============================================================================
__global__ __launch_bounds__(256, 1) void k_recfused(
    const float* __restrict__ Whh0g,
    const float* __restrict__ Wih1g, const float* __restrict__ Whh1g,
    const float* __restrict__ bih1g, const float* __restrict__ bhh1g,
    const float* __restrict__ h0ode,
    const float* __restrict__ oW1, const float* __restrict__ ob1,
    const float* __restrict__ oW2, const float* __restrict__ ob2,
    const float* __restrict__ oW3, const float* __restrict__ ob3)
{
    const int t = threadIdx.x;
    if (blockIdx.x == 128) {
        ode_body(t, h0ode, oW1, ob1, oW2, ob2, oW3, ob3);
        return;
    }
    const int w  = t >> 5, l = t & 31;
    const int gt = l >> 3;
    const int u  = (w << 3) | (l & 7);
    const int r  = gt * 64 + u;
    const int lb = l & 7;
    const unsigned FULL = 0xffffffffu;

    u64 wh0[32], wi1[32], wh1[32];
    {
        const u64* p0 = (const u64*)(Whh0g + r * 64);
        const u64* p1 = (const u64*)(Wih1g + r * 64);
        const u64* p2 = (const u64*)(Whh1g + r * 64);
#pragma unroll
        for (int k = 0; k < 32; ++k) { wh0[k] = p0[k]; wi1[k] = p1[k]; wh1[k] = p2[k]; }
    }
    const float bias1 = bih1g[r] + bhh1g[r];

    __shared__ __align__(16) float hs0[2][2][NHID];
    __shared__ __align__(16) float hs1[2][2][NHID];
    ((float*)hs0)[t] = 0.0f;   // 256 floats = both buffers
    ((float*)hs1)[t] = 0.0f;

    const int b0 = blockIdx.x * 2;
    const float* gA = g_gin0 + (size_t)b0 * NT * 256;
    const float* gB = gA + (size_t)NT * 256;
    float* e0 = g_env1 + (size_t)b0 * NT * NHID;
    float* e1 = e0 + (size_t)NT * NHID;
    const bool isg = (gt == 2);

    float c0A = 0.f, c0B = 0.f, c1A = 0.f, c1B = 0.f;

    float gnA = gA[r],        gnB = gB[r];          // gin for step 0
    float gxA = gA[256 + r],  gxB = gB[256 + r];    // gin for step 1
    __syncthreads();

    // ---- s = 0: L0 only; h0[-1] = 0 so gate = gin0[0] ----
    {
        float actA = isg ? ftanh(gnA) : fsig(gnA);
        float actB = isg ? ftanh(gnB) : fsig(gnB);
        float iA = __shfl_sync(FULL, actA, lb);
        float gA_ = __shfl_sync(FULL, actA, lb + 16);
        float oA = __shfl_sync(FULL, actA, lb + 24);
        float iB = __shfl_sync(FULL, actB, lb);
        float gB_ = __shfl_sync(FULL, actB, lb + 16);
        float oB = __shfl_sync(FULL, actB, lb + 24);
        c0A = iA * gA_;
        c0B = iB * gB_;
        float hA = oA * ftanh(c0A);
        float hB = oB * ftanh(c0B);
        if (gt == 0) { hs0[1][0][u] = hA; hs0[1][1][u] = hB; }
        gnA = gxA; gnB = gxB;
        gxA = gA[512 + r]; gxB = gB[512 + r];        // gin for step 2
        __syncthreads();
    }

    // ---- main loop s = 1 .. NT-1: both layers, merged k-loop ----
#pragma unroll 1
    for (int s = 1; s < NT; ++s) {
        const int cur = s & 1;
        const float* h0A = hs0[cur][0];
        const float* h0B = hs0[cur][1];
        const float* h1A = hs1[cur][0];
        const float* h1B = hs1[cur][1];

        u64 a0 = pack2(gnA, 0.f),   a1 = 0;   // L0 row A
        u64 b0 = pack2(gnB, 0.f),   b1 = 0;   // L0 row B
        u64 q0 = pack2(bias1, 0.f), q1 = 0;   // L1 row A
        u64 s0 = pack2(bias1, 0.f), s1 = 0;   // L1 row B
#pragma unroll
        for (int k = 0; k < NHID; k += 4) {
            ulonglong2 vA = *(const ulonglong2*)(h0A + k);
            ulonglong2 vB = *(const ulonglong2*)(h0B + k);
            ulonglong2 uA = *(const ulonglong2*)(h1A + k);
            ulonglong2 uB = *(const ulonglong2*)(h1B + k);
            const int kk = k >> 1;
            fma2(a0, wh0[kk], vA.x);  fma2(a1, wh0[kk+1], vA.y);
            fma2(b0, wh0[kk], vB.x);  fma2(b1, wh0[kk+1], vB.y);
            fma2(q0, wi1[kk], vA.x);  fma2(q1, wi1[kk+1], vA.y);
            fma2(q0, wh1[kk], uA.x);  fma2(q1, wh1[kk+1], uA.y);
            fma2(s0, wi1[kk], vB.x);  fma2(s1, wi1[kk+1], vB.y);
            fma2(s0, wh1[kk], uB.x);  fma2(s1, wh1[kk+1], uB.y);
        }
        gnA = gxA; gnB = gxB;
        if (s + 2 < NT) {
            gxA = gA[(size_t)(s + 2) * 256 + r];
            gxB = gB[(size_t)(s + 2) * 256 + r];
        }

        float p0A = hsum2(a0) + hsum2(a1);
        float p0B = hsum2(b0) + hsum2(b1);
        float p1A = hsum2(q0) + hsum2(q1);
        float p1B = hsum2(s0) + hsum2(s1);
        float act0A = isg ? ftanh(p0A) : fsig(p0A);
        float act0B = isg ? ftanh(p0B) : fsig(p0B);
        float act1A = isg ? ftanh(p1A) : fsig(p1A);
        float act1B = isg ? ftanh(p1B) : fsig(p1B);

        float i0A = __shfl_sync(FULL, act0A, lb);
        float f0A = __shfl_sync(FULL, act0A, lb + 8);
        float g0A = __shfl_sync(FULL, act0A, lb + 16);
        float o0A = __shfl_sync(FULL, act0A, lb + 24);
        float i0B = __shfl_sync(FULL, act0B, lb);
        float f0B = __shfl_sync(FULL, act0B, lb + 8);
        float g0B = __shfl_sync(FULL, act0B, lb + 16);
        float o0B = __shfl_sync(FULL, act0B, lb + 24);
        float i1A = __shfl_sync(FULL, act1A, lb);
        float f1A = __shfl_sync(FULL, act1A, lb + 8);
        float g1A = __shfl_sync(FULL, act1A, lb + 16);
        float o1A = __shfl_sync(FULL, act1A, lb + 24);
        float i1B = __shfl_sync(FULL, act1B, lb);
        float f1B = __shfl_sync(FULL, act1B, lb + 8);
        float g1B = __shfl_sync(FULL, act1B, lb + 16);
        float o1B = __shfl_sync(FULL, act1B, lb + 24);

        c0A = f0A * c0A + i0A * g0A;
        c0B = f0B * c0B + i0B * g0B;
        c1A = f1A * c1A + i1A * g1A;
        c1B = f1B * c1B + i1B * g1B;
        float h0nA = o0A * ftanh(c0A);
        float h0nB = o0B * ftanh(c0B);
        float h1nA = o1A * ftanh(c1A);
        float h1nB = o1B * ftanh(c1B);

        if (gt == 0) {
            hs0[cur ^ 1][0][u] = h0nA;
            hs0[cur ^ 1][1][u] = h0nB;
            hs1[cur ^ 1][0][u] = h1nA;
            hs1[cur ^ 1][1][u] = h1nB;
            e0[(size_t)(s - 1) * NHID + u] = h1nA;
            e1[(size_t)(s - 1) * NHID + u] = h1nB;
        }
        __syncthreads();
    }

    // ---- s = NT: L1 only, computing step NT-1 ----
    {
        const int cur = NT & 1;   // 0
        const float* h0A = hs0[cur][0];
        const float* h0B = hs0[cur][1];
        const float* h1A = hs1[cur][0];
        const float* h1B = hs1[cur][1];
        u64 q0 = pack2(bias1, 0.f), q1 = 0;
        u64 s0 = pack2(bias1, 0.f), s1 = 0;
#pragma unroll
        for (int k = 0; k < NHID; k += 4) {
            ulonglong2 vA = *(const ulonglong2*)(h0A + k);
            ulonglong2 vB = *(const ulonglong2*)(h0B + k);
            ulonglong2 uA = *(const ulonglong2*)(h1A + k);
            ulonglong2 uB = *(const ulonglong2*)(h1B + k);
            const int kk = k >> 1;
            fma2(q0, wi1[kk], vA.x);  fma2(q1, wi1[kk+1], vA.y);
            fma2(q0, wh1[kk], uA.x);  fma2(q1, wh1[kk+1], uA.y);
            fma2(s0, wi1[kk], vB.x);  fma2(s1, wi1[kk+1], vB.y);
            fma2(s0, wh1[kk], uB.x);  fma2(s1, wh1[kk+1], uB.y);
        }
        float p1A = hsum2(q0) + hsum2(q1);
        float p1B = hsum2(s0) + hsum2(s1);
        float act1A = isg ? ftanh(p1A) : fsig(p1A);
        float act1B = isg ? ftanh(p1B) : fsig(p1B);

        float i1A = __shfl_sync(FULL, act1A, lb);
        float f1A = __shfl_sync(FULL, act1A, lb + 8);
        float g1A = __shfl_sync(FULL, act1A, lb + 16);
        float o1A = __shfl_sync(FULL, act1A, lb + 24);
        float i1B = __shfl_sync(FULL, act1B, lb);
        float f1B = __shfl_sync(FULL, act1B, lb + 8);
        float g1B = __shfl_sync(FULL, act1B, lb + 16);
        float o1B = __shfl_sync(FULL, act1B, lb + 24);

        c1A = f1A * c1A + i1A * g1A;
        c1B = f1B * c1B + i1B * g1B;
        float h1nA = o1A * ftanh(c1A);
        float h1nB = o1B * ftanh(c1B);
        if (gt == 0) {
            e0[(size_t)(NT - 1) * NHID + u] = h1nA;
            e1[(size_t)(NT - 1) * NHID + u] = h1nB;
        }
    }
}

// ---------------- Kernel C: physics + fusion MLP + outputs ------------------
__global__ __launch_bounds__(256) void k_fusion(
    const int*   __restrict__ day_ids,
    const float* __restrict__ raw,
    const float* __restrict__ hdw, const float* __restrict__ hdb,
    const float* __restrict__ fW1, const float* __restrict__ fb1,
    const float* __restrict__ fW2, const float* __restrict__ fb2,
    const float* __restrict__ rW1, const float* __restrict__ rb1,
    const float* __restrict__ rW2, const float* __restrict__ rb2,
    float* __restrict__ out)
{
    const int tid = threadIdx.x;

    __shared__ __align__(16) float sW1[64 * 76];   // fus_W1 padded 73 -> 76
    __shared__ __align__(16) float sW2[64 * 64];
    __shared__ __align__(16) float sR1[32 * 64];
    __shared__ float sR2[32];
    __shared__ float sb1[64], sb2[64], srb1[32];
    __shared__ float shdw[8];
    __shared__ float sscal[2];

    for (int i = tid; i < 64 * 76; i += 256) {
        int j = i / 76, k = i - j * 76;
        sW1[i] = (k < 73) ? fW1[j * 73 + k] : 0.0f;
    }
    for (int i = tid; i < 64 * 64; i += 256) sW2[i] = fW2[i];
    for (int i = tid; i < 32 * 64; i += 256) sR1[i] = rW1[i];
    if (tid < 64) { sb1[tid] = fb1[tid]; sb2[tid] = fb2[tid]; }
    if (tid < 32) { sR2[tid] = rW2[tid]; srb1[tid] = rb1[tid]; }
    if (tid < 8)  shdw[tid] = hdw[tid];
    if (tid == 0) { sscal[0] = hdb[0]; sscal[1] = rb2[0]; }
    __syncthreads();

    const int idx = blockIdx.x * 256 + tid;       // grid = 2048 -> idx < NPOS
    const int b = idx >> 11;

    float z[76];
    const float4* ep = (const float4*)(g_env1 + (size_t)idx * NHID);
#pragma unroll
    for (int i = 0; i < 16; ++i) {
        float4 v = ep[i];
        z[4*i+0] = v.x; z[4*i+1] = v.y; z[4*i+2] = v.z; z[4*i+3] = v.w;
    }
    const int day = day_ids[b];
    float health[8];
#pragma unroll
    for (int i = 0; i < 8; ++i) { health[i] = g_traj[day * 8 + i]; z[64 + i] = health[i]; }

    float4 rv = ((const float4*)raw)[idx];
    float iphys = rv.x * 9.0f * (1.0f + 0.0005f * (rv.y - 0.5f));
    z[72] = iphys; z[73] = 0.f; z[74] = 0.f; z[75] = 0.f;

    float rawD = sscal[0];
#pragma unroll
    for (int i = 0; i < 8; ++i) rawD = fmaf(health[i], shdw[i], rawD);
    float D = fsig(rawD);

    // feat1 = relu(fus_W1 @ z + fb1)
    float f1[64];
#pragma unroll
    for (int j = 0; j < 64; j += 4) {
        float a0 = sb1[j], a1 = sb1[j+1], a2 = sb1[j+2], a3 = sb1[j+3];
#pragma unroll
        for (int k = 0; k < 76; k += 4) {
            float4 w0 = *(const float4*)(sW1 + (j+0) * 76 + k);
            float4 w1 = *(const float4*)(sW1 + (j+1) * 76 + k);
            float4 w2 = *(const float4*)(sW1 + (j+2) * 76 + k);
            float4 w3 = *(const float4*)(sW1 + (j+3) * 76 + k);
            a0 = fmaf(z[k], w0.x, a0); a0 = fmaf(z[k+1], w0.y, a0); a0 = fmaf(z[k+2], w0.z, a0); a0 = fmaf(z[k+3], w0.w, a0);
            a1 = fmaf(z[k], w1.x, a1); a1 = fmaf(z[k+1], w1.y, a1); a1 = fmaf(z[k+2], w1.z, a1); a1 = fmaf(z[k+3], w1.w, a1);
            a2 = fmaf(z[k], w2.x, a2); a2 = fmaf(z[k+1], w2.y, a2); a2 = fmaf(z[k+2], w2.z, a2); a2 = fmaf(z[k+3], w2.w, a2);
            a3 = fmaf(z[k], w3.x, a3); a3 = fmaf(z[k+1], w3.y, a3); a3 = fmaf(z[k+2], w3.z, a3); a3 = fmaf(z[k+3], w3.w, a3);
        }
        f1[j+0] = fmaxf(a0, 0.f); f1[j+1] = fmaxf(a1, 0.f);
        f1[j+2] = fmaxf(a2, 0.f); f1[j+3] = fmaxf(a3, 0.f);
    }

    // feat2 = relu(fus_W2 @ feat1 + fb2)
    float f2[64];
#pragma unroll
    for (int j = 0; j < 64; j += 4) {
        float a0 = sb2[j], a1 = sb2[j+1], a2 = sb2[j+2], a3 = sb2[j+3];
#pragma unroll
        for (int k = 0; k < 64; k += 4) {
            float4 w0 = *(const float4*)(sW2 + (j+0) * 64 + k);
            float4 w1 = *(const float4*)(sW2 + (j+1) * 64 + k);
            float4 w2 = *(const float4*)(sW2 + (j+2) * 64 + k);
            float4 w3 = *(const float4*)(sW2 + (j+3) * 64 + k);
            a0 = fmaf(f1[k], w0.x, a0); a0 = fmaf(f1[k+1], w0.y, a0); a0 = fmaf(f1[k+2], w0.z, a0); a0 = fmaf(f1[k+3], w0.w, a0);
            a1 = fmaf(f1[k], w1.x, a1); a1 = fmaf(f1[k+1], w1.y, a1); a1 = fmaf(f1[k+2], w1.z, a1); a1 = fmaf(f1[k+3], w1.w, a1);
            a2 = fmaf(f1[k], w2.x, a2); a2 = fmaf(f1[k+1], w2.y, a2); a2 = fmaf(f1[k+2], w2.z, a2); a2 = fmaf(f1[k+3], w2.w, a2);
            a3 = fmaf(f1[k], w3.x, a3); a3 = fmaf(f1[k+1], w3.y, a3); a3 = fmaf(f1[k+2], w3.z, a3); a3 = fmaf(f1[k+3], w3.w, a3);
        }
        f2[j+0] = fmaxf(a0, 0.f); f2[j+1] = fmaxf(a1, 0.f);
        f2[j+2] = fmaxf(a2, 0.f); f2[j+3] = fmaxf(a3, 0.f);
    }

    // r1 = relu(res_W1 @ feat2 + rb1)
    float r1[32];
#pragma unroll
    for (int j = 0; j < 32; j += 4) {
        float a0 = srb1[j], a1 = srb1[j+1], a2 = srb1[j+2], a3 = srb1[j+3];
#pragma unroll
        for (int k = 0; k < 64; k += 4) {
            float4 w0 = *(const float4*)(sR1 + (j+0) * 64 + k);
            float4 w1 = *(const float4*)(sR1 + (j+1) * 64 + k);
            float4 w2 = *(const float4*)(sR1 + (j+2) * 64 + k);
            float4 w3 = *(const float4*)(sR1 + (j+3) * 64 + k);
            a0 = fmaf(f2[k], w0.x, a0); a0 = fmaf(f2[k+1], w0.y, a0); a0 = fmaf(f2[k+2], w0.z, a0); a0 = fmaf(f2[k+3], w0.w, a0);
            a1 = fmaf(f2[k], w1.x, a1); a1 = fmaf(f2[k+1], w1.y, a1); a1 = fmaf(f2[k+2], w1.z, a1); a1 = fmaf(f2[k+3], w1.w, a1);
            a2 = fmaf(f2[k], w2.x, a2); a2 = fmaf(f2[k+1], w2.y, a2); a2 = fmaf(f2[k+2], w2.z, a2); a2 = fmaf(f2[k+3], w2.w, a2);
            a3 = fmaf(f2[k], w3.x, a3); a3 = fmaf(f2[k+1], w3.y, a3); a3 = fmaf(f2[k+2], w3.z, a3); a3 = fmaf(f2[k+3], w3.w, a3);
        }
        r1[j+0] = fmaxf(a0, 0.f); r1[j+1] = fmaxf(a1, 0.f);
        r1[j+2] = fmaxf(a2, 0.f); r1[j+3] = fmaxf(a3, 0.f);
    }

    // r = res_W2 @ r1 + rb2
    float a0 = sscal[1], a1 = 0.f, a2 = 0.f, a3 = 0.f;
#pragma unroll
    for (int k = 0; k < 32; k += 4) {
        a0 = fmaf(r1[k+0], sR2[k+0], a0);
        a1 = fmaf(r1[k+1], sR2[k+1], a1);
        a2 = fmaf(r1[k+2], sR2[k+2], a2);
        a3 = fmaf(r1[k+3], sR2[k+3], a3);
    }
    float r = (a0 + a1) + (a2 + a3);

    float ibase = D * iphys;
    out[(size_t)0 * NPOS + idx] = ibase + r;   // I_pred
    out[(size_t)1 * NPOS + idx] = iphys;       // I_phys
    out[(size_t)2 * NPOS + idx] = ibase;       // I_base
    out[(size_t)3 * NPOS + idx] = D;           // D
    out[(size_t)4 * NPOS + idx] = r;           // r
    float* ho = out + (size_t)5 * NPOS + (size_t)idx * 8;
#pragma unroll
    for (int i = 0; i < 8; ++i) ho[i] = health[i];  // health_seq
}

// ---------------- launch ----------------------------------------------------
extern "C" void kernel_launch(void* const* d_in, const int* in_sizes, int n_in,
                              void* d_out, int out_size)
{
    const float* X        = (const float*)d_in[0];
    const int*   day_ids  = (const int*)  d_in[1];
    const float* raw      = (const float*)d_in[2];
    const float* ih0      = (const float*)d_in[3];
    const float* oW1      = (const float*)d_in[4];
    const float* ob1      = (const float*)d_in[5];
    const float* oW2      = (const float*)d_in[6];
    const float* ob2      = (const float*)d_in[7];
    const float* oW3      = (const float*)d_in[8];
    const float* ob3      = (const float*)d_in[9];
    const float* Wih0     = (const float*)d_in[10];
    const float* Whh0     = (const float*)d_in[11];
    const float* bih0     = (const float*)d_in[12];
    const float* bhh0     = (const float*)d_in[13];
    const float* Wih1     = (const float*)d_in[14];
    const float* Whh1     = (const float*)d_in[15];
    const float* bih1     = (const float*)d_in[16];
    const float* bhh1     = (const float*)d_in[17];
    const float* hdw      = (const float*)d_in[18];
    const float* hdb      = (const float*)d_in[19];
    const float* fW1      = (const float*)d_in[20];
    const float* fb1      = (const float*)d_in[21];
    const float* fW2      = (const float*)d_in[22];
    const float* fb2      = (const float*)d_in[23];
    const float* rW1      = (const float*)d_in[24];
    const float* rb1      = (const float*)d_in[25];
    const float* rW2      = (const float*)d_in[26];
    const float* rb2      = (const float*)d_in[27];

    float* gin0;  cudaGetSymbolAddress((void**)&gin0, g_gin0);

    // L0 input projection (parallel GEMM).
    k_gates0<<<NPOS / 128, 256>>>(X, Wih0, bih0, bhh0, gin0);
    // Fused L0+L1 recurrence (skewed) + ODE hidden as CTA 128: one wave.
    k_recfused<<<129, 256>>>(Whh0, Wih1, Whh1, bih1, bhh1,
                             ih0, oW1, ob1, oW2, ob2, oW3, ob3);
    // Physics + fusion MLP + all outputs.
    k_fusion<<<NPOS / 256, 256>>>(day_ids, raw, hdw, hdb,
                                  fW1, fb1, fW2, fb2,
                                  rW1, rb1, rW2, rb2,
                                  (float*)d_out);
}

// round 8
// speedup vs baseline: 2.1053x; 1.0416x over previous
#include <cuda_runtime.h>
#include <cstdint>
#include <cstddef>

#define NBATCH 256
#define NT     2048
#define NFIN   32
#define NHID   64
#define NPOS   (NBATCH * NT)   // 524288

typedef unsigned long long u64;

// ---------------- scratch (static device globals: allocation-free) ----------
__device__ float g_env1[(size_t)NBATCH * NT * NHID];    // layer-1 LSTM output
__device__ float g_gin0[(size_t)NPOS * 256];            // L0 gate input-proj
__device__ float4 g_wh0s[8 * 16 * 32];                  // staged Whh0 (64 KB)
__device__ float g_traj[366 * 8];                       // ODE trajectory

// ---------------- fast activations (fp32, ~1e-6 rel err) -------------------
__device__ __forceinline__ float fsig(float x) {
    return __fdividef(1.0f, 1.0f + __expf(-x));
}
__device__ __forceinline__ float ftanh(float x) {
    float ax = fabsf(x);
    float e  = __expf(-2.0f * ax);
    float r  = __fdividef(1.0f - e, 1.0f + e);
    return copysignf(r, x);
}

// ---------------- packed f32x2 helpers --------------------------------------
__device__ __forceinline__ u64 pack2(float lo, float hi) {
    u64 r; asm("mov.b64 %0, {%1, %2};" : "=l"(r) : "f"(lo), "f"(hi)); return r;
}
__device__ __forceinline__ void fma2(u64& a, u64 w, u64 v) {
    asm("fma.rn.f32x2 %0, %1, %2, %0;" : "+l"(a) : "l"(w), "l"(v));
}
__device__ __forceinline__ float hsum2(u64 a) {
    float lo, hi; asm("mov.b64 {%0, %1}, %2;" : "=f"(lo), "=f"(hi) : "l"(a));
    return lo + hi;
}
// volatile LDG (prevents hoist/CSE across loop iterations)
__device__ __forceinline__ ulonglong2 ldg_v2u64(const void* p) {
    ulonglong2 r;
    asm volatile("ld.global.nc.v2.u64 {%0,%1}, [%2];"
                 : "=l"(r.x), "=l"(r.y) : "l"(p));
    return r;
}

// ---------------- ODE body (runs as blockIdx == 128 of fused rec) ----------
__device__ void ode_body(int tid,
                         const float* __restrict__ h0,
                         const float* __restrict__ W1, const float* __restrict__ b1,
                         const float* __restrict__ W2, const float* __restrict__ b2,
                         const float* __restrict__ W3, const float* __restrict__ b3)
{
    __shared__ float sInp[12];
    __shared__ float sz1[64];
    __shared__ float sz2[64];
    __shared__ float sk[6][8];
    __shared__ float shh[8];
    __shared__ __align__(16) float sW3[8 * 64];
    __shared__ float sb3[8];

    float w1r[9];
    float w2r[64];
    float b1j = 0.f, b2j = 0.f;
    if (tid < 64) {
#pragma unroll
        for (int k = 0; k < 9; ++k) w1r[k] = W1[tid * 9 + k];
#pragma unroll
        for (int k = 0; k < 64; ++k) w2r[k] = W2[tid * 64 + k];
        b1j = b1[tid];
        b2j = b2[tid];
    }
    for (int i = tid; i < 8 * 64; i += 256) sW3[i] = W3[i];
    if (tid < 8) {
        sb3[tid] = b3[tid];
        shh[tid] = h0[tid];
        g_traj[tid] = h0[tid];
    }
    __syncthreads();

    const float dt = 1.0f / 365.0f;

    for (int d = 0; d < 365; ++d) {
        float t0 = (float)d * dt;
#pragma unroll 1
        for (int s = 0; s < 6; ++s) {
            if (tid < 8) {
                float v = shh[tid];
                if (s == 1) v += dt * (0.2f * sk[0][tid]);
                else if (s == 2) v += dt * ((3.f/40.f)*sk[0][tid] + (9.f/40.f)*sk[1][tid]);
                else if (s == 3) v += dt * ((44.f/45.f)*sk[0][tid] - (56.f/15.f)*sk[1][tid] + (32.f/9.f)*sk[2][tid]);
                else if (s == 4) v += dt * ((19372.f/6561.f)*sk[0][tid] - (25360.f/2187.f)*sk[1][tid]
                                          + (64448.f/6561.f)*sk[2][tid] - (212.f/729.f)*sk[3][tid]);
                else if (s == 5) v += dt * ((9017.f/3168.f)*sk[0][tid] - (355.f/33.f)*sk[1][tid]
                                          + (46732.f/5247.f)*sk[2][tid] + (49.f/176.f)*sk[3][tid]
                                          - (5103.f/18656.f)*sk[4][tid]);
                sInp[tid] = v;
            }
            if (tid == 8) {
                float cn;
                if (s == 0) cn = 0.0f;
                else if (s == 1) cn = 0.2f;
                else if (s == 2) cn = 0.3f;
                else if (s == 3) cn = 0.8f;
                else if (s == 4) cn = 8.f/9.f;
                else cn = 1.0f;
                sInp[8] = t0 + cn * dt;
            }
            __syncthreads();
            if (tid < 64) {
                float a = b1j;
#pragma unroll
                for (int k = 0; k < 9; ++k) a = fmaf(w1r[k], sInp[k], a);
                sz1[tid] = ftanh(a);
            }
            __syncthreads();
            if (tid < 64) {
                float a0 = b2j, a1 = 0.f, a2 = 0.f, a3 = 0.f;
#pragma unroll
                for (int k = 0; k < 64; k += 4) {
                    a0 = fmaf(w2r[k+0], sz1[k+0], a0);
                    a1 = fmaf(w2r[k+1], sz1[k+1], a1);
                    a2 = fmaf(w2r[k+2], sz1[k+2], a2);
                    a3 = fmaf(w2r[k+3], sz1[k+3], a3);
                }
                sz2[tid] = ftanh((a0 + a1) + (a2 + a3));
            }
            __syncthreads();
            if (tid < 8) {
                float a0 = sb3[tid], a1 = 0.f, a2 = 0.f, a3 = 0.f;
#pragma unroll
                for (int k = 0; k < 64; k += 4) {
                    a0 = fmaf(sW3[tid*64 + k+0], sz2[k+0], a0);
                    a1 = fmaf(sW3[tid*64 + k+1], sz2[k+1], a1);
                    a2 = fmaf(sW3[tid*64 + k+2], sz2[k+2], a2);
                    a3 = fmaf(sW3[tid*64 + k+3], sz2[k+3], a3);
                }
                sk[s][tid] = (a0 + a1) + (a2 + a3);
            }
            __syncthreads();
        }
        if (tid < 8) {
            float hn = shh[tid] + dt * ((35.f/384.f)   * sk[0][tid]
                                      + (500.f/1113.f) * sk[2][tid]
                                      + (125.f/192.f)  * sk[3][tid]
                                      - (2187.f/6784.f)* sk[4][tid]
                                      + (11.f/84.f)    * sk[5][tid]);
            shh[tid] = hn;
            g_traj[(d + 1) * 8 + tid] = hn;
        }
        __syncthreads();
    }
}

// ============================================================================
// Stage Whh0 into lane-coalesced layout:
// g_wh0s[(w*16+kp)*32 + l] = float4 of Whh0[r(w,l)][4kp .. 4kp+3]
// where r = (l>>3)*64 + (w<<3) + (l&7).
// ============================================================================
__global__ void k_stage(const float* __restrict__ Whh0)
{
    int e = blockIdx.x * 256 + threadIdx.x;   // grid 16 x 256 = 4096
    int l  = e & 31;
    int kp = (e >> 5) & 15;
    int w  = e >> 9;
    int r  = (l >> 3) * 64 + (w << 3) + (l & 7);
    g_wh0s[e] = *(const float4*)(Whh0 + r * 64 + kp * 4);
}

// ============================================================================
// L0 gate input-projection GEMM (f32x2).
// gin[pos][r] = sum_k Wih0[r][k] * x[pos][k] + (bih[r]+bhh[r])
// ============================================================================
__global__ __launch_bounds__(256) void k_gates0(
    const float* __restrict__ X,
    const float* __restrict__ Wih,
    const float* __restrict__ bih, const float* __restrict__ bhh,
    float* __restrict__ gout)
{
    __shared__ __align__(16) float xs[128 * NFIN];      // 16 kB
    const int tid = threadIdx.x;
    const size_t pos0 = (size_t)blockIdx.x * 128;

    const float4* xg = (const float4*)(X + pos0 * NFIN);
    float4* xs4 = (float4*)xs;
#pragma unroll
    for (int i = 0; i < 4; ++i) xs4[tid + 256 * i] = xg[tid + 256 * i];

    u64 wrp[16];
    {
        const u64* wp = (const u64*)(Wih + tid * NFIN);
#pragma unroll
        for (int k = 0; k < 16; ++k) wrp[k] = wp[k];
    }
    const float bias = bih[tid] + bhh[tid];
    __syncthreads();

#pragma unroll 1
    for (int p = 0; p < 128; p += 4) {
        u64 a0 = pack2(bias, 0.f), a1 = pack2(bias, 0.f);
        u64 a2 = pack2(bias, 0.f), a3 = pack2(bias, 0.f);
        const ulonglong2* x0 = (const ulonglong2*)(xs + (p+0) * NFIN);
        const ulonglong2* x1 = (const ulonglong2*)(xs + (p+1) * NFIN);
        const ulonglong2* x2 = (const ulonglong2*)(xs + (p+2) * NFIN);
        const ulonglong2* x3 = (const ulonglong2*)(xs + (p+3) * NFIN);
#pragma unroll
        for (int k2 = 0; k2 < 8; ++k2) {
            ulonglong2 v0 = x0[k2], v1 = x1[k2], v2 = x2[k2], v3 = x3[k2];
            fma2(a0, wrp[2*k2], v0.x); fma2(a0, wrp[2*k2+1], v0.y);
            fma2(a1, wrp[2*k2], v1.x); fma2(a1, wrp[2*k2+1], v1.y);
            fma2(a2, wrp[2*k2], v2.x); fma2(a2, wrp[2*k2+1], v2.y);
            fma2(a3, wrp[2*k2], v3.x); fma2(a3, wrp[2*k2+1], v3.y);
        }
        gout[(pos0 + p + 0) * 256 + tid] = hsum2(a0);
        gout[(pos0 + p + 1) * 256 + tid] = hsum2(a1);
        gout[(pos0 + p + 2) * 256 + tid] = hsum2(a2);
        gout[(pos0 + p + 3) * 256 + tid] = hsum2(a3);
    }
}

// ============================================================================
// Fused recurrence: L0 + L1 with 1-step skew.
// Persistent regs: Wih1, Whh1 rows (64 u64). Whh0 streamed each step from the
// staged coalesced layout (L1-resident; volatile LDG prevents reg promotion).
// 2 batch rows per CTA, 128 CTAs (+ ODE at blockIdx 128): one wave.
// ============================================================================
__global__ __launch_bounds__(256, 1) void k_recfused(
    const float* __restrict__ Wih1g, const float* __restrict__ Whh1g,
    const float* __restrict__ bih1g, const float* __restrict__ bhh1g,
    const float* __restrict__ h0ode,
    const float* __restrict__ oW1, const float* __restrict__ ob1,
    const float* __restrict__ oW2, const float* __restrict__ ob2,
    const float* __restrict__ oW3, const float* __restrict__ ob3)
{
    const int t = threadIdx.x;
    if (blockIdx.x == 128) {
        ode_body(t, h0ode, oW1, ob1, oW2, ob2, oW3, ob3);
        return;
    }
    const int w  = t >> 5, l = t & 31;
    const int gt = l >> 3;
    const int u  = (w << 3) | (l & 7);
    const int r  = gt * 64 + u;
    const int lb = l & 7;
    const unsigned FULL = 0xffffffffu;

    u64 wi1[32], wh1[32];
    {
        const u64* p1 = (const u64*)(Wih1g + r * 64);
        const u64* p2 = (const u64*)(Whh1g + r * 64);
#pragma unroll
        for (int k = 0; k < 32; ++k) { wi1[k] = p1[k]; wh1[k] = p2[k]; }
    }
    const float bias1 = bih1g[r] + bhh1g[r];
    const char* wsbase = (const char*)(g_wh0s + (w * 16) * 32 + l);

    __shared__ __align__(16) float hs0[2][2][NHID];
    __shared__ __align__(16) float hs1[2][2][NHID];
    ((float*)hs0)[t] = 0.0f;
    ((float*)hs1)[t] = 0.0f;

    const int b0 = blockIdx.x * 2;
    const float* gA = g_gin0 + (size_t)b0 * NT * 256;
    const float* gB = gA + (size_t)NT * 256;
    float* e0 = g_env1 + (size_t)b0 * NT * NHID;
    float* e1 = e0 + (size_t)NT * NHID;
    const bool isg = (gt == 2);

    float c0A = 0.f, c0B = 0.f, c1A = 0.f, c1B = 0.f;

    float gnA = gA[r],        gnB = gB[r];          // gin for step 0
    float gxA = gA[256 + r],  gxB = gB[256 + r];    // gin for step 1
    __syncthreads();

    // ---- s = 0: L0 only; h0[-1] = 0 so gate = gin0[0] ----
    {
        float actA = isg ? ftanh(gnA) : fsig(gnA);
        float actB = isg ? ftanh(gnB) : fsig(gnB);
        float iA = __shfl_sync(FULL, actA, lb);
        float gA_ = __shfl_sync(FULL, actA, lb + 16);
        float oA = __shfl_sync(FULL, actA, lb + 24);
        float iB = __shfl_sync(FULL, actB, lb);
        float gB_ = __shfl_sync(FULL, actB, lb + 16);
        float oB = __shfl_sync(FULL, actB, lb + 24);
        c0A = iA * gA_;
        c0B = iB * gB_;
        float hA = oA * ftanh(c0A);
        float hB = oB * ftanh(c0B);
        if (gt == 0) { hs0[1][0][u] = hA; hs0[1][1][u] = hB; }
        gnA = gxA; gnB = gxB;
        gxA = gA[512 + r]; gxB = gB[512 + r];        // gin for step 2
        __syncthreads();
    }

    // ---- main loop s = 1 .. NT-1 ----
#pragma unroll 1
    for (int s = 1; s < NT; ++s) {
        const int cur = s & 1;
        const float* h0A = hs0[cur][0];
        const float* h0B = hs0[cur][1];
        const float* h1A = hs1[cur][0];
        const float* h1B = hs1[cur][1];

        // stream Whh0 row (coalesced; L1-hit after first step)
        u64 ws[32];
#pragma unroll
        for (int kp = 0; kp < 16; ++kp) {
            ulonglong2 u2 = ldg_v2u64(wsbase + (size_t)kp * 512);
            ws[2*kp] = u2.x; ws[2*kp+1] = u2.y;
        }

        u64 a0 = pack2(gnA, 0.f),   a1 = 0;   // L0 row A
        u64 b0 = pack2(gnB, 0.f),   b1 = 0;   // L0 row B
        u64 q0 = pack2(bias1, 0.f), q1 = 0;   // L1 row A
        u64 s0 = pack2(bias1, 0.f), s1 = 0;   // L1 row B
#pragma unroll
        for (int k = 0; k < NHID; k += 4) {
            ulonglong2 vA = *(const ulonglong2*)(h0A + k);
            ulonglong2 vB = *(const ulonglong2*)(h0B + k);
            ulonglong2 uA = *(const ulonglong2*)(h1A + k);
            ulonglong2 uB = *(const ulonglong2*)(h1B + k);
            const int kk = k >> 1;
            fma2(q0, wi1[kk], vA.x);  fma2(q1, wi1[kk+1], vA.y);
            fma2(q0, wh1[kk], uA.x);  fma2(q1, wh1[kk+1], uA.y);
            fma2(s0, wi1[kk], vB.x);  fma2(s1, wi1[kk+1], vB.y);
            fma2(s0, wh1[kk], uB.x);  fma2(s1, wh1[kk+1], uB.y);
            fma2(a0, ws[kk], vA.x);   fma2(a1, ws[kk+1], vA.y);
            fma2(b0, ws[kk], vB.x);   fma2(b1, ws[kk+1], vB.y);
        }
        gnA = gxA; gnB = gxB;
        if (s + 2 < NT) {
            gxA = gA[(size_t)(s + 2) * 256 + r];
            gxB = gB[(size_t)(s + 2) * 256 + r];
        }

        float p0A = hsum2(a0) + hsum2(a1);
        float p0B = hsum2(b0) + hsum2(b1);
        float p1A = hsum2(q0) + hsum2(q1);
        float p1B = hsum2(s0) + hsum2(s1);
        float act0A = isg ? ftanh(p0A) : fsig(p0A);
        float act0B = isg ? ftanh(p0B) : fsig(p0B);
        float act1A = isg ? ftanh(p1A) : fsig(p1A);
        float act1B = isg ? ftanh(p1B) : fsig(p1B);

        float i0A = __shfl_sync(FULL, act0A, lb);
        float f0A = __shfl_sync(FULL, act0A, lb + 8);
        float g0A = __shfl_sync(FULL, act0A, lb + 16);
        float o0A = __shfl_sync(FULL, act0A, lb + 24);
        float i0B = __shfl_sync(FULL, act0B, lb);
        float f0B = __shfl_sync(FULL, act0B, lb + 8);
        float g0B = __shfl_sync(FULL, act0B, lb + 16);
        float o0B = __shfl_sync(FULL, act0B, lb + 24);
        float i1A = __shfl_sync(FULL, act1A, lb);
        float f1A = __shfl_sync(FULL, act1A, lb + 8);
        float g1A = __shfl_sync(FULL, act1A, lb + 16);
        float o1A = __shfl_sync(FULL, act1A, lb + 24);
        float i1B = __shfl_sync(FULL, act1B, lb);
        float f1B = __shfl_sync(FULL, act1B, lb + 8);
        float g1B = __shfl_sync(FULL, act1B, lb + 16);
        float o1B = __shfl_sync(FULL, act1B, lb + 24);

        c0A = f0A * c0A + i0A * g0A;
        c0B = f0B * c0B + i0B * g0B;
        c1A = f1A * c1A + i1A * g1A;
        c1B = f1B * c1B + i1B * g1B;
        float h0nA = o0A * ftanh(c0A);
        float h0nB = o0B * ftanh(c0B);
        float h1nA = o1A * ftanh(c1A);
        float h1nB = o1B * ftanh(c1B);

        if (gt == 0) {
            hs0[cur ^ 1][0][u] = h0nA;
            hs0[cur ^ 1][1][u] = h0nB;
            hs1[cur ^ 1][0][u] = h1nA;
            hs1[cur ^ 1][1][u] = h1nB;
            e0[(size_t)(s - 1) * NHID + u] = h1nA;
            e1[(size_t)(s - 1) * NHID + u] = h1nB;
        }
        __syncthreads();
    }

    // ---- s = NT: L1 only, computing step NT-1 ----
    {
        const int cur = NT & 1;   // 0
        const float* h0A = hs0[cur][0];
        const float* h0B = hs0[cur][1];
        const float* h1A = hs1[cur][0];
        const float* h1B = hs1[cur][1];
        u64 q0 = pack2(bias1, 0.f), q1 = 0;
        u64 s0 = pack2(bias1, 0.f), s1 = 0;
#pragma unroll
        for (int k = 0; k < NHID; k += 4) {
            ulonglong2 vA = *(const ulonglong2*)(h0A + k);
            ulonglong2 vB = *(const ulonglong2*)(h0B + k);
            ulonglong2 uA = *(const ulonglong2*)(h1A + k);
            ulonglong2 uB = *(const ulonglong2*)(h1B + k);
            const int kk = k >> 1;
            fma2(q0, wi1[kk], vA.x);  fma2(q1, wi1[kk+1], vA.y);
            fma2(q0, wh1[kk], uA.x);  fma2(q1, wh1[kk+1], uA.y);
            fma2(s0, wi1[kk], vB.x);  fma2(s1, wi1[kk+1], vB.y);
            fma2(s0, wh1[kk], uB.x);  fma2(s1, wh1[kk+1], uB.y);
        }
        float p1A = hsum2(q0) + hsum2(q1);
        float p1B = hsum2(s0) + hsum2(s1);
        float act1A = isg ? ftanh(p1A) : fsig(p1A);
        float act1B = isg ? ftanh(p1B) : fsig(p1B);

        float i1A = __shfl_sync(FULL, act1A, lb);
        float f1A = __shfl_sync(FULL, act1A, lb + 8);
        float g1A = __shfl_sync(FULL, act1A, lb + 16);
        float o1A = __shfl_sync(FULL, act1A, lb + 24);
        float i1B = __shfl_sync(FULL, act1B, lb);
        float f1B = __shfl_sync(FULL, act1B, lb + 8);
        float g1B = __shfl_sync(FULL, act1B, lb + 16);
        float o1B = __shfl_sync(FULL, act1B, lb + 24);

        c1A = f1A * c1A + i1A * g1A;
        c1B = f1B * c1B + i1B * g1B;
        float h1nA = o1A * ftanh(c1A);
        float h1nB = o1B * ftanh(c1B);
        if (gt == 0) {
            e0[(size_t)(NT - 1) * NHID + u] = h1nA;
            e1[(size_t)(NT - 1) * NHID + u] = h1nB;
        }
    }
}

// ---------------- Kernel C: physics + fusion MLP + outputs (f32x2) ----------
__global__ __launch_bounds__(256) void k_fusion(
    const int*   __restrict__ day_ids,
    const float* __restrict__ raw,
    const float* __restrict__ hdw, const float* __restrict__ hdb,
    const float* __restrict__ fW1, const float* __restrict__ fb1,
    const float* __restrict__ fW2, const float* __restrict__ fb2,
    const float* __restrict__ rW1, const float* __restrict__ rb1,
    const float* __restrict__ rW2, const float* __restrict__ rb2,
    float* __restrict__ out)
{
    const int tid = threadIdx.x;

    __shared__ __align__(16) float sW1[64 * 76];   // fus_W1 padded 73 -> 76
    __shared__ __align__(16) float sW2[64 * 64];
    __shared__ __align__(16) float sR1[32 * 64];
    __shared__ __align__(16) float sR2[32];
    __shared__ float sb1[64], sb2[64], srb1[32];
    __shared__ float shdw[8];
    __shared__ float sscal[2];

    for (int i = tid; i < 64 * 76; i += 256) {
        int j = i / 76, k = i - j * 76;
        sW1[i] = (k < 73) ? fW1[j * 73 + k] : 0.0f;
    }
    for (int i = tid; i < 64 * 64; i += 256) sW2[i] = fW2[i];
    for (int i = tid; i < 32 * 64; i += 256) sR1[i] = rW1[i];
    if (tid < 64) { sb1[tid] = fb1[tid]; sb2[tid] = fb2[tid]; }
    if (tid < 32) { sR2[tid] = rW2[tid]; srb1[tid] = rb1[tid]; }
    if (tid < 8)  shdw[tid] = hdw[tid];
    if (tid == 0) { sscal[0] = hdb[0]; sscal[1] = rb2[0]; }
    __syncthreads();

    const int idx = blockIdx.x * 256 + tid;       // grid = 2048 -> idx < NPOS
    const int b = idx >> 11;

    // build packed input z (76 floats = 38 u64 pairs)
    u64 zp[38];
    const float4* ep = (const float4*)(g_env1 + (size_t)idx * NHID);
#pragma unroll
    for (int i = 0; i < 16; ++i) {
        float4 v = ep[i];
        zp[2*i]   = pack2(v.x, v.y);
        zp[2*i+1] = pack2(v.z, v.w);
    }
    const int day = day_ids[b];
    float health[8];
#pragma unroll
    for (int i = 0; i < 8; ++i) health[i] = g_traj[day * 8 + i];
#pragma unroll
    for (int i = 0; i < 4; ++i) zp[32 + i] = pack2(health[2*i], health[2*i+1]);

    float4 rv = ((const float4*)raw)[idx];
    float iphys = rv.x * 9.0f * (1.0f + 0.0005f * (rv.y - 0.5f));
    zp[36] = pack2(iphys, 0.f);
    zp[37] = 0;

    float rawD = sscal[0];
#pragma unroll
    for (int i = 0; i < 8; ++i) rawD = fmaf(health[i], shdw[i], rawD);
    float D = fsig(rawD);

    // feat1 = relu(fus_W1 @ z + fb1)  -> packed pairs
    u64 f1p[32];
#pragma unroll
    for (int j = 0; j < 64; j += 2) {
        u64 a0 = pack2(sb1[j], 0.f), a1 = pack2(sb1[j+1], 0.f);
        const ulonglong2* w0 = (const ulonglong2*)(sW1 + (j+0) * 76);
        const ulonglong2* w1 = (const ulonglong2*)(sW1 + (j+1) * 76);
#pragma unroll
        for (int k2 = 0; k2 < 19; ++k2) {
            ulonglong2 x0 = w0[k2], x1 = w1[k2];
            fma2(a0, x0.x, zp[2*k2]); fma2(a0, x0.y, zp[2*k2+1]);
            fma2(a1, x1.x, zp[2*k2]); fma2(a1, x1.y, zp[2*k2+1]);
        }
        f1p[j >> 1] = pack2(fmaxf(hsum2(a0), 0.f), fmaxf(hsum2(a1), 0.f));
    }

    // feat2 = relu(fus_W2 @ feat1 + fb2)
    u64 f2p[32];
#pragma unroll
    for (int j = 0; j < 64; j += 2) {
        u64 a0 = pack2(sb2[j], 0.f), a1 = pack2(sb2[j+1], 0.f);
        const ulonglong2* w0 = (const ulonglong2*)(sW2 + (j+0) * 64);
        const ulonglong2* w1 = (const ulonglong2*)(sW2 + (j+1) * 64);
#pragma unroll
        for (int k2 = 0; k2 < 16; ++k2) {
            ulonglong2 x0 = w0[k2], x1 = w1[k2];
            fma2(a0, x0.x, f1p[2*k2]); fma2(a0, x0.y, f1p[2*k2+1]);
            fma2(a1, x1.x, f1p[2*k2]); fma2(a1, x1.y, f1p[2*k2+1]);
        }
        f2p[j >> 1] = pack2(fmaxf(hsum2(a0), 0.f), fmaxf(hsum2(a1), 0.f));
    }

    // r1 = relu(res_W1 @ feat2 + rb1)
    u64 r1p[16];
#pragma unroll
    for (int j = 0; j < 32; j += 2) {
        u64 a0 = pack2(srb1[j], 0.f), a1 = pack2(srb1[j+1], 0.f);
        const ulonglong2* w0 = (const ulonglong2*)(sR1 + (j+0) * 64);
        const ulonglong2* w1 = (const ulonglong2*)(sR1 + (j+1) * 64);
#pragma unroll
        for (int k2 = 0; k2 < 16; ++k2) {
            ulonglong2 x0 = w0[k2], x1 = w1[k2];
            fma2(a0, x0.x, f2p[2*k2]); fma2(a0, x0.y, f2p[2*k2+1]);
            fma2(a1, x1.x, f2p[2*k2]); fma2(a1, x1.y, f2p[2*k2+1]);
        }
        r1p[j >> 1] = pack2(fmaxf(hsum2(a0), 0.f), fmaxf(hsum2(a1), 0.f));
    }

    // r = res_W2 @ r1 + rb2
    u64 acc = pack2(sscal[1], 0.f);
    const u64* r2w = (const u64*)sR2;
#pragma unroll
    for (int k = 0; k < 16; ++k) fma2(acc, r2w[k], r1p[k]);
    float r = hsum2(acc);

    float ibase = D * iphys;
    out[(size_t)0 * NPOS + idx] = ibase + r;   // I_pred
    out[(size_t)1 * NPOS + idx] = iphys;       // I_phys
    out[(size_t)2 * NPOS + idx] = ibase;       // I_base
    out[(size_t)3 * NPOS + idx] = D;           // D
    out[(size_t)4 * NPOS + idx] = r;           // r
    float* ho = out + (size_t)5 * NPOS + (size_t)idx * 8;
#pragma unroll
    for (int i = 0; i < 8; ++i) ho[i] = health[i];  // health_seq
}

// ---------------- launch ----------------------------------------------------
extern "C" void kernel_launch(void* const* d_in, const int* in_sizes, int n_in,
                              void* d_out, int out_size)
{
    const float* X        = (const float*)d_in[0];
    const int*   day_ids  = (const int*)  d_in[1];
    const float* raw      = (const float*)d_in[2];
    const float* ih0      = (const float*)d_in[3];
    const float* oW1      = (const float*)d_in[4];
    const float* ob1      = (const float*)d_in[5];
    const float* oW2      = (const float*)d_in[6];
    const float* ob2      = (const float*)d_in[7];
    const float* oW3      = (const float*)d_in[8];
    const float* ob3      = (const float*)d_in[9];
    const float* Wih0     = (const float*)d_in[10];
    const float* Whh0     = (const float*)d_in[11];
    const float* bih0     = (const float*)d_in[12];
    const float* bhh0     = (const float*)d_in[13];
    const float* Wih1     = (const float*)d_in[14];
    const float* Whh1     = (const float*)d_in[15];
    const float* bih1     = (const float*)d_in[16];
    const float* bhh1     = (const float*)d_in[17];
    const float* hdw      = (const float*)d_in[18];
    const float* hdb      = (const float*)d_in[19];
    const float* fW1      = (const float*)d_in[20];
    const float* fb1      = (const float*)d_in[21];
    const float* fW2      = (const float*)d_in[22];
    const float* fb2      = (const float*)d_in[23];
    const float* rW1      = (const float*)d_in[24];
    const float* rb1      = (const float*)d_in[25];
    const float* rW2      = (const float*)d_in[26];
    const float* rb2      = (const float*)d_in[27];

    float* gin0;  cudaGetSymbolAddress((void**)&gin0, g_gin0);

    // Stage Whh0 into the coalesced layout.
    k_stage<<<16, 256>>>(Whh0);
    // L0 input projection (parallel GEMM, f32x2).
    k_gates0<<<NPOS / 128, 256>>>(X, Wih0, bih0, bhh0, gin0);
    // Fused L0+L1 recurrence (skewed) + ODE hidden as CTA 128: one wave.
    k_recfused<<<129, 256>>>(Wih1, Whh1, bih1, bhh1,
                             ih0, oW1, ob1, oW2, ob2, oW3, ob3);
    // Physics + fusion MLP + all outputs (f32x2).
    k_fusion<<<NPOS / 256, 256>>>(day_ids, raw, hdw, hdb,
                                  fW1, fb1, fW2, fb2,
                                  rW1, rb1, rW2, rb2,
                                  (float*)d_out);
}

// round 9
// speedup vs baseline: 2.2457x; 1.0667x over previous
#include <cuda_runtime.h>
#include <cstdint>
#include <cstddef>

#define NBATCH 256
#define NT     2048
#define NFIN   32
#define NHID   64
#define NPOS   (NBATCH * NT)   // 524288

typedef unsigned long long u64;

// ---------------- scratch (static device globals: allocation-free) ----------
__device__ float g_env1[(size_t)NBATCH * NT * NHID];    // layer-1 LSTM output
__device__ float g_gin0[(size_t)NPOS * 256];            // L0 gate input-proj
__device__ float g_f1[(size_t)NPOS * NHID];             // fusion feat1 (transposed pairs)
__device__ float4 g_wh0s[8 * 16 * 32];                  // staged Whh0 (64 KB)
__device__ float g_traj[366 * 8];                       // ODE trajectory

// ---------------- fast activations (fp32, ~1e-6 rel err) -------------------
__device__ __forceinline__ float fsig(float x) {
    return __fdividef(1.0f, 1.0f + __expf(-x));
}
__device__ __forceinline__ float ftanh(float x) {
    float ax = fabsf(x);
    float e  = __expf(-2.0f * ax);
    float r  = __fdividef(1.0f - e, 1.0f + e);
    return copysignf(r, x);
}

// ---------------- packed f32x2 helpers --------------------------------------
__device__ __forceinline__ u64 pack2(float lo, float hi) {
    u64 r; asm("mov.b64 %0, {%1, %2};" : "=l"(r) : "f"(lo), "f"(hi)); return r;
}
__device__ __forceinline__ void fma2(u64& a, u64 w, u64 v) {
    asm("fma.rn.f32x2 %0, %1, %2, %0;" : "+l"(a) : "l"(w), "l"(v));
}
__device__ __forceinline__ float hsum2(u64 a) {
    float lo, hi; asm("mov.b64 {%0, %1}, %2;" : "=f"(lo), "=f"(hi) : "l"(a));
    return lo + hi;
}
__device__ __forceinline__ void unpack2(u64 a, float& lo, float& hi) {
    asm("mov.b64 {%0, %1}, %2;" : "=f"(lo), "=f"(hi) : "l"(a));
}
// volatile LDG (prevents hoist/CSE across loop iterations)
__device__ __forceinline__ ulonglong2 ldg_v2u64(const void* p) {
    ulonglong2 r;
    asm volatile("ld.global.nc.v2.u64 {%0,%1}, [%2];"
                 : "=l"(r.x), "=l"(r.y) : "l"(p));
    return r;
}

// ---------------- ODE body (runs as blockIdx == 128 of fused rec) ----------
__device__ void ode_body(int tid,
                         const float* __restrict__ h0,
                         const float* __restrict__ W1, const float* __restrict__ b1,
                         const float* __restrict__ W2, const float* __restrict__ b2,
                         const float* __restrict__ W3, const float* __restrict__ b3)
{
    __shared__ float sInp[12];
    __shared__ float sz1[64];
    __shared__ float sz2[64];
    __shared__ float sk[6][8];
    __shared__ float shh[8];
    __shared__ __align__(16) float sW3[8 * 64];
    __shared__ float sb3[8];

    float w1r[9];
    float w2r[64];
    float b1j = 0.f, b2j = 0.f;
    if (tid < 64) {
#pragma unroll
        for (int k = 0; k < 9; ++k) w1r[k] = W1[tid * 9 + k];
#pragma unroll
        for (int k = 0; k < 64; ++k) w2r[k] = W2[tid * 64 + k];
        b1j = b1[tid];
        b2j = b2[tid];
    }
    for (int i = tid; i < 8 * 64; i += 256) sW3[i] = W3[i];
    if (tid < 8) {
        sb3[tid] = b3[tid];
        shh[tid] = h0[tid];
        g_traj[tid] = h0[tid];
    }
    __syncthreads();

    const float dt = 1.0f / 365.0f;

    for (int d = 0; d < 365; ++d) {
        float t0 = (float)d * dt;
#pragma unroll 1
        for (int s = 0; s < 6; ++s) {
            if (tid < 8) {
                float v = shh[tid];
                if (s == 1) v += dt * (0.2f * sk[0][tid]);
                else if (s == 2) v += dt * ((3.f/40.f)*sk[0][tid] + (9.f/40.f)*sk[1][tid]);
                else if (s == 3) v += dt * ((44.f/45.f)*sk[0][tid] - (56.f/15.f)*sk[1][tid] + (32.f/9.f)*sk[2][tid]);
                else if (s == 4) v += dt * ((19372.f/6561.f)*sk[0][tid] - (25360.f/2187.f)*sk[1][tid]
                                          + (64448.f/6561.f)*sk[2][tid] - (212.f/729.f)*sk[3][tid]);
                else if (s == 5) v += dt * ((9017.f/3168.f)*sk[0][tid] - (355.f/33.f)*sk[1][tid]
                                          + (46732.f/5247.f)*sk[2][tid] + (49.f/176.f)*sk[3][tid]
                                          - (5103.f/18656.f)*sk[4][tid]);
                sInp[tid] = v;
            }
            if (tid == 8) {
                float cn;
                if (s == 0) cn = 0.0f;
                else if (s == 1) cn = 0.2f;
                else if (s == 2) cn = 0.3f;
                else if (s == 3) cn = 0.8f;
                else if (s == 4) cn = 8.f/9.f;
                else cn = 1.0f;
                sInp[8] = t0 + cn * dt;
            }
            __syncthreads();
            if (tid < 64) {
                float a = b1j;
#pragma unroll
                for (int k = 0; k < 9; ++k) a = fmaf(w1r[k], sInp[k], a);
                sz1[tid] = ftanh(a);
            }
            __syncthreads();
            if (tid < 64) {
                float a0 = b2j, a1 = 0.f, a2 = 0.f, a3 = 0.f;
#pragma unroll
                for (int k = 0; k < 64; k += 4) {
                    a0 = fmaf(w2r[k+0], sz1[k+0], a0);
                    a1 = fmaf(w2r[k+1], sz1[k+1], a1);
                    a2 = fmaf(w2r[k+2], sz1[k+2], a2);
                    a3 = fmaf(w2r[k+3], sz1[k+3], a3);
                }
                sz2[tid] = ftanh((a0 + a1) + (a2 + a3));
            }
            __syncthreads();
            if (tid < 8) {
                float a0 = sb3[tid], a1 = 0.f, a2 = 0.f, a3 = 0.f;
#pragma unroll
                for (int k = 0; k < 64; k += 4) {
                    a0 = fmaf(sW3[tid*64 + k+0], sz2[k+0], a0);
                    a1 = fmaf(sW3[tid*64 + k+1], sz2[k+1], a1);
                    a2 = fmaf(sW3[tid*64 + k+2], sz2[k+2], a2);
                    a3 = fmaf(sW3[tid*64 + k+3], sz2[k+3], a3);
                }
                sk[s][tid] = (a0 + a1) + (a2 + a3);
            }
            __syncthreads();
        }
        if (tid < 8) {
            float hn = shh[tid] + dt * ((35.f/384.f)   * sk[0][tid]
                                      + (500.f/1113.f) * sk[2][tid]
                                      + (125.f/192.f)  * sk[3][tid]
                                      - (2187.f/6784.f)* sk[4][tid]
                                      + (11.f/84.f)    * sk[5][tid]);
            shh[tid] = hn;
            g_traj[(d + 1) * 8 + tid] = hn;
        }
        __syncthreads();
    }
}

// ============================================================================
// Stage Whh0 into lane-coalesced layout.
// ============================================================================
__global__ void k_stage(const float* __restrict__ Whh0)
{
    int e = blockIdx.x * 256 + threadIdx.x;   // grid 16 x 256 = 4096
    int l  = e & 31;
    int kp = (e >> 5) & 15;
    int w  = e >> 9;
    int r  = (l >> 3) * 64 + (w << 3) + (l & 7);
    g_wh0s[e] = *(const float4*)(Whh0 + r * 64 + kp * 4);
}

// ============================================================================
// L0 gate input-projection GEMM (f32x2).
// ============================================================================
__global__ __launch_bounds__(256) void k_gates0(
    const float* __restrict__ X,
    const float* __restrict__ Wih,
    const float* __restrict__ bih, const float* __restrict__ bhh,
    float* __restrict__ gout)
{
    __shared__ __align__(16) float xs[128 * NFIN];      // 16 kB
    const int tid = threadIdx.x;
    const size_t pos0 = (size_t)blockIdx.x * 128;

    const float4* xg = (const float4*)(X + pos0 * NFIN);
    float4* xs4 = (float4*)xs;
#pragma unroll
    for (int i = 0; i < 4; ++i) xs4[tid + 256 * i] = xg[tid + 256 * i];

    u64 wrp[16];
    {
        const u64* wp = (const u64*)(Wih + tid * NFIN);
#pragma unroll
        for (int k = 0; k < 16; ++k) wrp[k] = wp[k];
    }
    const float bias = bih[tid] + bhh[tid];
    __syncthreads();

#pragma unroll 1
    for (int p = 0; p < 128; p += 4) {
        u64 a0 = pack2(bias, 0.f), a1 = pack2(bias, 0.f);
        u64 a2 = pack2(bias, 0.f), a3 = pack2(bias, 0.f);
        const ulonglong2* x0 = (const ulonglong2*)(xs + (p+0) * NFIN);
        const ulonglong2* x1 = (const ulonglong2*)(xs + (p+1) * NFIN);
        const ulonglong2* x2 = (const ulonglong2*)(xs + (p+2) * NFIN);
        const ulonglong2* x3 = (const ulonglong2*)(xs + (p+3) * NFIN);
#pragma unroll
        for (int k2 = 0; k2 < 8; ++k2) {
            ulonglong2 v0 = x0[k2], v1 = x1[k2], v2 = x2[k2], v3 = x3[k2];
            fma2(a0, wrp[2*k2], v0.x); fma2(a0, wrp[2*k2+1], v0.y);
            fma2(a1, wrp[2*k2], v1.x); fma2(a1, wrp[2*k2+1], v1.y);
            fma2(a2, wrp[2*k2], v2.x); fma2(a2, wrp[2*k2+1], v2.y);
            fma2(a3, wrp[2*k2], v3.x); fma2(a3, wrp[2*k2+1], v3.y);
        }
        gout[(pos0 + p + 0) * 256 + tid] = hsum2(a0);
        gout[(pos0 + p + 1) * 256 + tid] = hsum2(a1);
        gout[(pos0 + p + 2) * 256 + tid] = hsum2(a2);
        gout[(pos0 + p + 3) * 256 + tid] = hsum2(a3);
    }
}

// ============================================================================
// Fused recurrence: L0 + L1 with 1-step skew (unchanged from R7 — near floor).
// ============================================================================
__global__ __launch_bounds__(256, 1) void k_recfused(
    const float* __restrict__ Wih1g, const float* __restrict__ Whh1g,
    const float* __restrict__ bih1g, const float* __restrict__ bhh1g,
    const float* __restrict__ h0ode,
    const float* __restrict__ oW1, const float* __restrict__ ob1,
    const float* __restrict__ oW2, const float* __restrict__ ob2,
    const float* __restrict__ oW3, const float* __restrict__ ob3)
{
    const int t = threadIdx.x;
    if (blockIdx.x == 128) {
        ode_body(t, h0ode, oW1, ob1, oW2, ob2, oW3, ob3);
        return;
    }
    const int w  = t >> 5, l = t & 31;
    const int gt = l >> 3;
    const int u  = (w << 3) | (l & 7);
    const int r  = gt * 64 + u;
    const int lb = l & 7;
    const unsigned FULL = 0xffffffffu;

    u64 wi1[32], wh1[32];
    {
        const u64* p1 = (const u64*)(Wih1g + r * 64);
        const u64* p2 = (const u64*)(Whh1g + r * 64);
#pragma unroll
        for (int k = 0; k < 32; ++k) { wi1[k] = p1[k]; wh1[k] = p2[k]; }
    }
    const float bias1 = bih1g[r] + bhh1g[r];
    const char* wsbase = (const char*)(g_wh0s + (w * 16) * 32 + l);

    __shared__ __align__(16) float hs0[2][2][NHID];
    __shared__ __align__(16) float hs1[2][2][NHID];
    ((float*)hs0)[t] = 0.0f;
    ((float*)hs1)[t] = 0.0f;

    const int b0 = blockIdx.x * 2;
    const float* gA = g_gin0 + (size_t)b0 * NT * 256;
    const float* gB = gA + (size_t)NT * 256;
    float* e0 = g_env1 + (size_t)b0 * NT * NHID;
    float* e1 = e0 + (size_t)NT * NHID;
    const bool isg = (gt == 2);

    float c0A = 0.f, c0B = 0.f, c1A = 0.f, c1B = 0.f;

    float gnA = gA[r],        gnB = gB[r];          // gin for step 0
    float gxA = gA[256 + r],  gxB = gB[256 + r];    // gin for step 1
    __syncthreads();

    // ---- s = 0: L0 only; h0[-1] = 0 so gate = gin0[0] ----
    {
        float actA = isg ? ftanh(gnA) : fsig(gnA);
        float actB = isg ? ftanh(gnB) : fsig(gnB);
        float iA = __shfl_sync(FULL, actA, lb);
        float gA_ = __shfl_sync(FULL, actA, lb + 16);
        float oA = __shfl_sync(FULL, actA, lb + 24);
        float iB = __shfl_sync(FULL, actB, lb);
        float gB_ = __shfl_sync(FULL, actB, lb + 16);
        float oB = __shfl_sync(FULL, actB, lb + 24);
        c0A = iA * gA_;
        c0B = iB * gB_;
        float hA = oA * ftanh(c0A);
        float hB = oB * ftanh(c0B);
        if (gt == 0) { hs0[1][0][u] = hA; hs0[1][1][u] = hB; }
        gnA = gxA; gnB = gxB;
        gxA = gA[512 + r]; gxB = gB[512 + r];        // gin for step 2
        __syncthreads();
    }

    // ---- main loop s = 1 .. NT-1 ----
#pragma unroll 1
    for (int s = 1; s < NT; ++s) {
        const int cur = s & 1;
        const float* h0A = hs0[cur][0];
        const float* h0B = hs0[cur][1];
        const float* h1A = hs1[cur][0];
        const float* h1B = hs1[cur][1];

        // stream Whh0 row (coalesced; L1-hit after first step)
        u64 ws[32];
#pragma unroll
        for (int kp = 0; kp < 16; ++kp) {
            ulonglong2 u2 = ldg_v2u64(wsbase + (size_t)kp * 512);
            ws[2*kp] = u2.x; ws[2*kp+1] = u2.y;
        }

        u64 a0 = pack2(gnA, 0.f),   a1 = 0;   // L0 row A
        u64 b0 = pack2(gnB, 0.f),   b1 = 0;   // L0 row B
        u64 q0 = pack2(bias1, 0.f), q1 = 0;   // L1 row A
        u64 s0 = pack2(bias1, 0.f), s1 = 0;   // L1 row B
#pragma unroll
        for (int k = 0; k < NHID; k += 4) {
            ulonglong2 vA = *(const ulonglong2*)(h0A + k);
            ulonglong2 vB = *(const ulonglong2*)(h0B + k);
            ulonglong2 uA = *(const ulonglong2*)(h1A + k);
            ulonglong2 uB = *(const ulonglong2*)(h1B + k);
            const int kk = k >> 1;
            fma2(q0, wi1[kk], vA.x);  fma2(q1, wi1[kk+1], vA.y);
            fma2(q0, wh1[kk], uA.x);  fma2(q1, wh1[kk+1], uA.y);
            fma2(s0, wi1[kk], vB.x);  fma2(s1, wi1[kk+1], vB.y);
            fma2(s0, wh1[kk], uB.x);  fma2(s1, wh1[kk+1], uB.y);
            fma2(a0, ws[kk], vA.x);   fma2(a1, ws[kk+1], vA.y);
            fma2(b0, ws[kk], vB.x);   fma2(b1, ws[kk+1], vB.y);
        }
        gnA = gxA; gnB = gxB;
        if (s + 2 < NT) {
            gxA = gA[(size_t)(s + 2) * 256 + r];
            gxB = gB[(size_t)(s + 2) * 256 + r];
        }

        float p0A = hsum2(a0) + hsum2(a1);
        float p0B = hsum2(b0) + hsum2(b1);
        float p1A = hsum2(q0) + hsum2(q1);
        float p1B = hsum2(s0) + hsum2(s1);
        float act0A = isg ? ftanh(p0A) : fsig(p0A);
        float act0B = isg ? ftanh(p0B) : fsig(p0B);
        float act1A = isg ? ftanh(p1A) : fsig(p1A);
        float act1B = isg ? ftanh(p1B) : fsig(p1B);

        float i0A = __shfl_sync(FULL, act0A, lb);
        float f0A = __shfl_sync(FULL, act0A, lb + 8);
        float g0A = __shfl_sync(FULL, act0A, lb + 16);
        float o0A = __shfl_sync(FULL, act0A, lb + 24);
        float i0B = __shfl_sync(FULL, act0B, lb);
        float f0B = __shfl_sync(FULL, act0B, lb + 8);
        float g0B = __shfl_sync(FULL, act0B, lb + 16);
        float o0B = __shfl_sync(FULL, act0B, lb + 24);
        float i1A = __shfl_sync(FULL, act1A, lb);
        float f1A = __shfl_sync(FULL, act1A, lb + 8);
        float g1A = __shfl_sync(FULL, act1A, lb + 16);
        float o1A = __shfl_sync(FULL, act1A, lb + 24);
        float i1B = __shfl_sync(FULL, act1B, lb);
        float f1B = __shfl_sync(FULL, act1B, lb + 8);
        float g1B = __shfl_sync(FULL, act1B, lb + 16);
        float o1B = __shfl_sync(FULL, act1B, lb + 24);

        c0A = f0A * c0A + i0A * g0A;
        c0B = f0B * c0B + i0B * g0B;
        c1A = f1A * c1A + i1A * g1A;
        c1B = f1B * c1B + i1B * g1B;
        float h0nA = o0A * ftanh(c0A);
        float h0nB = o0B * ftanh(c0B);
        float h1nA = o1A * ftanh(c1A);
        float h1nB = o1B * ftanh(c1B);

        if (gt == 0) {
            hs0[cur ^ 1][0][u] = h0nA;
            hs0[cur ^ 1][1][u] = h0nB;
            hs1[cur ^ 1][0][u] = h1nA;
            hs1[cur ^ 1][1][u] = h1nB;
            e0[(size_t)(s - 1) * NHID + u] = h1nA;
            e1[(size_t)(s - 1) * NHID + u] = h1nB;
        }
        __syncthreads();
    }

    // ---- s = NT: L1 only, computing step NT-1 ----
    {
        const int cur = NT & 1;   // 0
        const float* h0A = hs0[cur][0];
        const float* h0B = hs0[cur][1];
        const float* h1A = hs1[cur][0];
        const float* h1B = hs1[cur][1];
        u64 q0 = pack2(bias1, 0.f), q1 = 0;
        u64 s0 = pack2(bias1, 0.f), s1 = 0;
#pragma unroll
        for (int k = 0; k < NHID; k += 4) {
            ulonglong2 vA = *(const ulonglong2*)(h0A + k);
            ulonglong2 vB = *(const ulonglong2*)(h0B + k);
            ulonglong2 uA = *(const ulonglong2*)(h1A + k);
            ulonglong2 uB = *(const ulonglong2*)(h1B + k);
            const int kk = k >> 1;
            fma2(q0, wi1[kk], vA.x);  fma2(q1, wi1[kk+1], vA.y);
            fma2(q0, wh1[kk], uA.x);  fma2(q1, wh1[kk+1], uA.y);
            fma2(s0, wi1[kk], vB.x);  fma2(s1, wi1[kk+1], vB.y);
            fma2(s0, wh1[kk], uB.x);  fma2(s1, wh1[kk+1], uB.y);
        }
        float p1A = hsum2(q0) + hsum2(q1);
        float p1B = hsum2(s0) + hsum2(s1);
        float act1A = isg ? ftanh(p1A) : fsig(p1A);
        float act1B = isg ? ftanh(p1B) : fsig(p1B);

        float i1A = __shfl_sync(FULL, act1A, lb);
        float f1A = __shfl_sync(FULL, act1A, lb + 8);
        float g1A = __shfl_sync(FULL, act1A, lb + 16);
        float o1A = __shfl_sync(FULL, act1A, lb + 24);
        float i1B = __shfl_sync(FULL, act1B, lb);
        float f1B = __shfl_sync(FULL, act1B, lb + 8);
        float g1B = __shfl_sync(FULL, act1B, lb + 16);
        float o1B = __shfl_sync(FULL, act1B, lb + 24);

        c1A = f1A * c1A + i1A * g1A;
        c1B = f1B * c1B + i1B * g1B;
        float h1nA = o1A * ftanh(c1A);
        float h1nB = o1B * ftanh(c1B);
        if (gt == 0) {
            e0[(size_t)(NT - 1) * NHID + u] = h1nA;
            e1[(size_t)(NT - 1) * NHID + u] = h1nB;
        }
    }
}

// ============================================================================
// Fusion stage A: feat1 = relu(fus_W1 @ z + fb1).
// Low-reg (~110) -> 2 CTAs/SM. f1 stored pair-major transposed:
// ((u64*)g_f1)[j2 * NPOS + idx] = {f1[2j2], f1[2j2+1]}  (coalesced both ways).
// ============================================================================
__global__ __launch_bounds__(256, 2) void k_fusA(
    const int*   __restrict__ day_ids,
    const float* __restrict__ raw,
    const float* __restrict__ fW1, const float* __restrict__ fb1)
{
    const int tid = threadIdx.x;
    __shared__ __align__(16) float sW1[64 * 76];   // fus_W1 padded 73 -> 76
    __shared__ float sb1[64];

    for (int i = tid; i < 64 * 76; i += 256) {
        int j = i / 76, k = i - j * 76;
        sW1[i] = (k < 73) ? fW1[j * 73 + k] : 0.0f;
    }
    if (tid < 64) sb1[tid] = fb1[tid];
    __syncthreads();

    const int idx = blockIdx.x * 256 + tid;
    const int b = idx >> 11;

    u64 zp[38];
    const float4* ep = (const float4*)(g_env1 + (size_t)idx * NHID);
#pragma unroll
    for (int i = 0; i < 16; ++i) {
        float4 v = ep[i];
        zp[2*i]   = pack2(v.x, v.y);
        zp[2*i+1] = pack2(v.z, v.w);
    }
    const int day = day_ids[b];
#pragma unroll
    for (int i = 0; i < 4; ++i)
        zp[32 + i] = pack2(g_traj[day * 8 + 2*i], g_traj[day * 8 + 2*i + 1]);

    float4 rv = ((const float4*)raw)[idx];
    float iphys = rv.x * 9.0f * (1.0f + 0.0005f * (rv.y - 0.5f));
    zp[36] = pack2(iphys, 0.f);
    zp[37] = 0;

    u64* f1out = (u64*)g_f1;
#pragma unroll 1
    for (int j = 0; j < 64; j += 2) {
        u64 a0 = pack2(sb1[j], 0.f), a1 = pack2(sb1[j+1], 0.f);
        const ulonglong2* w0 = (const ulonglong2*)(sW1 + (j+0) * 76);
        const ulonglong2* w1 = (const ulonglong2*)(sW1 + (j+1) * 76);
#pragma unroll
        for (int k2 = 0; k2 < 19; ++k2) {
            ulonglong2 x0 = w0[k2], x1 = w1[k2];
            fma2(a0, x0.x, zp[2*k2]); fma2(a0, x0.y, zp[2*k2+1]);
            fma2(a1, x1.x, zp[2*k2]); fma2(a1, x1.y, zp[2*k2+1]);
        }
        f1out[(size_t)(j >> 1) * NPOS + idx] =
            pack2(fmaxf(hsum2(a0), 0.f), fmaxf(hsum2(a1), 0.f));
    }
}

// ============================================================================
// Fusion stage B: f1 -> f2 -> r1 -> outputs. f2 is streamed straight into the
// r1 accumulators (no f2 array). Peak regs ~128 -> 2 CTAs/SM.
// ============================================================================
__global__ __launch_bounds__(256, 2) void k_fusB(
    const int*   __restrict__ day_ids,
    const float* __restrict__ raw,
    const float* __restrict__ hdw, const float* __restrict__ hdb,
    const float* __restrict__ fW2, const float* __restrict__ fb2,
    const float* __restrict__ rW1, const float* __restrict__ rb1,
    const float* __restrict__ rW2, const float* __restrict__ rb2,
    float* __restrict__ out)
{
    const int tid = threadIdx.x;

    __shared__ __align__(16) float sW2[64 * 64];    // 16 kB (row-major)
    __shared__ __align__(16) u64   sR1t[64 * 16];   // 8 kB: [k][J] = {W[2J][k],W[2J+1][k]}
    __shared__ __align__(16) float sR2[32];
    __shared__ float sb2[64], srb1[32];
    __shared__ float shdw[8];
    __shared__ float sscal[2];

    for (int i = tid; i < 64 * 64; i += 256) sW2[i] = fW2[i];
    for (int i = tid; i < 64 * 16; i += 256) {
        int k = i >> 4, J = i & 15;
        sR1t[i] = pack2(rW1[(2*J) * 64 + k], rW1[(2*J+1) * 64 + k]);
    }
    if (tid < 64) sb2[tid] = fb2[tid];
    if (tid < 32) { sR2[tid] = rW2[tid]; srb1[tid] = rb1[tid]; }
    if (tid < 8)  shdw[tid] = hdw[tid];
    if (tid == 0) { sscal[0] = hdb[0]; sscal[1] = rb2[0]; }
    __syncthreads();

    const int idx = blockIdx.x * 256 + tid;
    const int b = idx >> 11;

    // load f1 (pair-major transposed; coalesced)
    u64 f1p[32];
    const u64* f1in = (const u64*)g_f1;
#pragma unroll
    for (int k2 = 0; k2 < 32; ++k2)
        f1p[k2] = f1in[(size_t)k2 * NPOS + idx];

    // r1 accumulators (init with bias)
    u64 r1acc[16];
#pragma unroll
    for (int J = 0; J < 16; ++J) r1acc[J] = pack2(srb1[2*J], srb1[2*J+1]);

    // f2 streamed into r1
#pragma unroll 1
    for (int jp = 0; jp < 32; ++jp) {           // f2 features (2jp, 2jp+1)
        u64 a0 = pack2(sb2[2*jp], 0.f), a1 = pack2(sb2[2*jp+1], 0.f);
        const ulonglong2* w0 = (const ulonglong2*)(sW2 + (2*jp+0) * 64);
        const ulonglong2* w1 = (const ulonglong2*)(sW2 + (2*jp+1) * 64);
#pragma unroll
        for (int k2 = 0; k2 < 16; ++k2) {
            ulonglong2 x0 = w0[k2], x1 = w1[k2];
            fma2(a0, x0.x, f1p[2*k2]); fma2(a0, x0.y, f1p[2*k2+1]);
            fma2(a1, x1.x, f1p[2*k2]); fma2(a1, x1.y, f1p[2*k2+1]);
        }
        float f2a = fmaxf(hsum2(a0), 0.f);
        float f2b = fmaxf(hsum2(a1), 0.f);
        u64 f2lo = pack2(f2a, f2a);
        u64 f2hi = pack2(f2b, f2b);
        const u64* wra = sR1t + (2*jp) * 16;
        const u64* wrb = sR1t + (2*jp+1) * 16;
#pragma unroll
        for (int J = 0; J < 16; ++J) {
            fma2(r1acc[J], wra[J], f2lo);
            fma2(r1acc[J], wrb[J], f2hi);
        }
    }

    // r = res_W2 @ relu(r1) + rb2
    u64 racc = pack2(sscal[1], 0.f);
    const u64* r2w = (const u64*)sR2;
#pragma unroll
    for (int J = 0; J < 16; ++J) {
        float lo, hi; unpack2(r1acc[J], lo, hi);
        fma2(racc, r2w[J], pack2(fmaxf(lo, 0.f), fmaxf(hi, 0.f)));
    }
    float r = hsum2(racc);

    // physics / D / outputs
    const int day = day_ids[b];
    float health[8];
#pragma unroll
    for (int i = 0; i < 8; ++i) health[i] = g_traj[day * 8 + i];
    float4 rv = ((const float4*)raw)[idx];
    float iphys = rv.x * 9.0f * (1.0f + 0.0005f * (rv.y - 0.5f));
    float rawD = sscal[0];
#pragma unroll
    for (int i = 0; i < 8; ++i) rawD = fmaf(health[i], shdw[i], rawD);
    float D = fsig(rawD);

    float ibase = D * iphys;
    out[(size_t)0 * NPOS + idx] = ibase + r;   // I_pred
    out[(size_t)1 * NPOS + idx] = iphys;       // I_phys
    out[(size_t)2 * NPOS + idx] = ibase;       // I_base
    out[(size_t)3 * NPOS + idx] = D;           // D
    out[(size_t)4 * NPOS + idx] = r;           // r
    float* ho = out + (size_t)5 * NPOS + (size_t)idx * 8;
#pragma unroll
    for (int i = 0; i < 8; ++i) ho[i] = health[i];  // health_seq
}

// ---------------- launch ----------------------------------------------------
extern "C" void kernel_launch(void* const* d_in, const int* in_sizes, int n_in,
                              void* d_out, int out_size)
{
    const float* X        = (const float*)d_in[0];
    const int*   day_ids  = (const int*)  d_in[1];
    const float* raw      = (const float*)d_in[2];
    const float* ih0      = (const float*)d_in[3];
    const float* oW1      = (const float*)d_in[4];
    const float* ob1      = (const float*)d_in[5];
    const float* oW2      = (const float*)d_in[6];
    const float* ob2      = (const float*)d_in[7];
    const float* oW3      = (const float*)d_in[8];
    const float* ob3      = (const float*)d_in[9];
    const float* Wih0     = (const float*)d_in[10];
    const float* Whh0     = (const float*)d_in[11];
    const float* bih0     = (const float*)d_in[12];
    const float* bhh0     = (const float*)d_in[13];
    const float* Wih1     = (const float*)d_in[14];
    const float* Whh1     = (const float*)d_in[15];
    const float* bih1     = (const float*)d_in[16];
    const float* bhh1     = (const float*)d_in[17];
    const float* hdw      = (const float*)d_in[18];
    const float* hdb      = (const float*)d_in[19];
    const float* fW1      = (const float*)d_in[20];
    const float* fb1      = (const float*)d_in[21];
    const float* fW2      = (const float*)d_in[22];
    const float* fb2      = (const float*)d_in[23];
    const float* rW1      = (const float*)d_in[24];
    const float* rb1      = (const float*)d_in[25];
    const float* rW2      = (const float*)d_in[26];
    const float* rb2      = (const float*)d_in[27];

    float* gin0;  cudaGetSymbolAddress((void**)&gin0, g_gin0);

    // Stage Whh0 into the coalesced layout.
    k_stage<<<16, 256>>>(Whh0);
    // L0 input projection (parallel GEMM, f32x2).
    k_gates0<<<NPOS / 128, 256>>>(X, Wih0, bih0, bhh0, gin0);
    // Fused L0+L1 recurrence (skewed) + ODE hidden as CTA 128: one wave.
    k_recfused<<<129, 256>>>(Wih1, Whh1, bih1, bhh1,
                             ih0, oW1, ob1, oW2, ob2, oW3, ob3);
    // Fusion stage A: feat1 (2 CTAs/SM).
    k_fusA<<<NPOS / 256, 256>>>(day_ids, raw, fW1, fb1);
    // Fusion stage B: feat2 -> residual -> outputs (2 CTAs/SM).
    k_fusB<<<NPOS / 256, 256>>>(day_ids, raw, hdw, hdb,
                                fW2, fb2, rW1, rb1, rW2, rb2,
                                (float*)d_out);
}